// round 1
// baseline (speedup 1.0000x reference)
#include <cuda_runtime.h>
#include <math.h>

#define S_LEN 2048
#define HID   5120
#define NH    40
#define HD    128
#define QKV_N (3*HID)   // 15360

// ---- flash-attention tiling ----
#define BQ  64
#define BKV 64
#define QT_STR 68    // Qt/Kt row stride (transposed [HD][BQ+pad]); %4==0 for float4
#define VS_STR 132   // Vs row stride ([BKV][HD+pad])
#define PS_STR 68
#define FLASH_SMEM_FLOATS (2*HD*QT_STR + BKV*VS_STR + BQ*PS_STR)
#define FLASH_SMEM_BYTES  (FLASH_SMEM_FLOATS*4)   // 120832 bytes

// Scratch (allocation-free rule: __device__ globals)
__device__ float g_qkv[(size_t)S_LEN * QKV_N];   // [s][3*HID]: Q | K | V packed
__device__ float g_attno[(size_t)S_LEN * HID];   // attention output [s][nh*hd]

// ============================================================================
// GEMM (TN): C[m,n] = sum_k A[m*K+k] * B[n*K+k]
// Block tile 128x128, K-tile 16, 256 threads, 8x8 per-thread register tile.
// ============================================================================
__global__ __launch_bounds__(256, 2)
void gemm_tn_kernel(const float* __restrict__ A, const float* __restrict__ B,
                    float* __restrict__ C, int M, int N, int K) {
    __shared__ float As[16][128];
    __shared__ float Bs[16][128];

    const int tid = threadIdx.x;
    const int ty = tid >> 4;        // 0..15
    const int tx = tid & 15;        // 0..15
    const int m0 = blockIdx.y * 128;
    const int n0 = blockIdx.x * 128;

    const int lrow = tid >> 2;          // 0..63
    const int lseg = (tid & 3) << 2;    // 0,4,8,12

    float acc[8][8];
#pragma unroll
    for (int i = 0; i < 8; i++)
#pragma unroll
        for (int j = 0; j < 8; j++) acc[i][j] = 0.0f;

    const float* Ap = A + (size_t)m0 * K;
    const float* Bp = B + (size_t)n0 * K;

    for (int k0 = 0; k0 < K; k0 += 16) {
        float4 a0 = *(const float4*)(Ap + (size_t)lrow      * K + k0 + lseg);
        float4 a1 = *(const float4*)(Ap + (size_t)(lrow+64) * K + k0 + lseg);
        float4 b0 = *(const float4*)(Bp + (size_t)lrow      * K + k0 + lseg);
        float4 b1 = *(const float4*)(Bp + (size_t)(lrow+64) * K + k0 + lseg);

        __syncthreads();   // previous tile fully consumed
        As[lseg+0][lrow]    = a0.x; As[lseg+1][lrow]    = a0.y;
        As[lseg+2][lrow]    = a0.z; As[lseg+3][lrow]    = a0.w;
        As[lseg+0][lrow+64] = a1.x; As[lseg+1][lrow+64] = a1.y;
        As[lseg+2][lrow+64] = a1.z; As[lseg+3][lrow+64] = a1.w;
        Bs[lseg+0][lrow]    = b0.x; Bs[lseg+1][lrow]    = b0.y;
        Bs[lseg+2][lrow]    = b0.z; Bs[lseg+3][lrow]    = b0.w;
        Bs[lseg+0][lrow+64] = b1.x; Bs[lseg+1][lrow+64] = b1.y;
        Bs[lseg+2][lrow+64] = b1.z; Bs[lseg+3][lrow+64] = b1.w;
        __syncthreads();

#pragma unroll
        for (int kk = 0; kk < 16; kk++) {
            float a[8], b[8];
            *(float4*)&a[0] = *(const float4*)&As[kk][ty*8];
            *(float4*)&a[4] = *(const float4*)&As[kk][ty*8 + 4];
            *(float4*)&b[0] = *(const float4*)&Bs[kk][tx*8];
            *(float4*)&b[4] = *(const float4*)&Bs[kk][tx*8 + 4];
#pragma unroll
            for (int i = 0; i < 8; i++)
#pragma unroll
                for (int j = 0; j < 8; j++)
                    acc[i][j] = fmaf(a[i], b[j], acc[i][j]);
        }
    }

#pragma unroll
    for (int i = 0; i < 8; i++) {
        float* cp = C + (size_t)(m0 + ty*8 + i) * N + n0 + tx*8;
        *(float4*)cp       = make_float4(acc[i][0], acc[i][1], acc[i][2], acc[i][3]);
        *(float4*)(cp + 4) = make_float4(acc[i][4], acc[i][5], acc[i][6], acc[i][7]);
    }
}

// ============================================================================
// Flash attention (fp32, causal). Grid (S/BQ, NH), 256 threads.
// Q/K/V read straight from packed g_qkv (no reorder pass needed).
// Per-thread: 4x4 score tile (16x16 thread grid), 4x8 output tile.
// ============================================================================
__global__ __launch_bounds__(256, 1)
void flash_attn_kernel(const float* __restrict__ qkv, float* __restrict__ out) {
    extern __shared__ float sm[];
    float* Qt = sm;                         // [HD][QT_STR]  (transposed: Qt[d][q])
    float* Kt = Qt + HD * QT_STR;           // [HD][QT_STR]  (transposed: Kt[d][kv])
    float* Vs = Kt + HD * QT_STR;           // [BKV][VS_STR] (natural: Vs[kv][d])
    float* Ps = Vs + BKV * VS_STR;          // [BQ][PS_STR]

    const int head = blockIdx.y;
    const int qb   = blockIdx.x;
    const int q0   = qb * BQ;
    const int tid  = threadIdx.x;
    const int ty   = tid >> 4;   // 0..15  -> score rows ty*4..+3
    const int tx   = tid & 15;   // 0..15  -> score cols tx*4..+3, out cols tx*8..+7
    const int lseg = tid & 31;   // d-segment (4 floats)
    const int lr0  = tid >> 5;   // 0..7

    const float scale = 1.0f / sqrtf((float)HD);

    // Load Q tile (transposed into Qt[d][q]); global reads fully coalesced.
#pragma unroll
    for (int it = 0; it < 8; it++) {
        int q = it * 8 + lr0;
        float4 v = *(const float4*)&qkv[(size_t)(q0 + q) * QKV_N + head * HD + lseg * 4];
        Qt[(lseg*4 + 0) * QT_STR + q] = v.x;
        Qt[(lseg*4 + 1) * QT_STR + q] = v.y;
        Qt[(lseg*4 + 2) * QT_STR + q] = v.z;
        Qt[(lseg*4 + 3) * QT_STR + q] = v.w;
    }

    float m_i[4], l_i[4], o_acc[4][8];
#pragma unroll
    for (int i = 0; i < 4; i++) {
        m_i[i] = -1e30f; l_i[i] = 0.0f;
#pragma unroll
        for (int j = 0; j < 8; j++) o_acc[i][j] = 0.0f;
    }

    for (int kb = 0; kb <= qb; kb++) {
        const int k0 = kb * BKV;

        __syncthreads();  // prior-iter consumers of Kt/Vs done (also covers Qt load, iter 0)

        // Load K (transposed) and V (natural)
#pragma unroll
        for (int it = 0; it < 8; it++) {
            int kv = it * 8 + lr0;
            const float* kp = &qkv[(size_t)(k0 + kv) * QKV_N +   HID + head * HD + lseg * 4];
            const float* vp = &qkv[(size_t)(k0 + kv) * QKV_N + 2*HID + head * HD + lseg * 4];
            float4 kk = *(const float4*)kp;
            Kt[(lseg*4 + 0) * QT_STR + kv] = kk.x;
            Kt[(lseg*4 + 1) * QT_STR + kv] = kk.y;
            Kt[(lseg*4 + 2) * QT_STR + kv] = kk.z;
            Kt[(lseg*4 + 3) * QT_STR + kv] = kk.w;
            *(float4*)&Vs[kv * VS_STR + lseg * 4] = *(const float4*)vp;
        }
        __syncthreads();

        // S tile: s[i][j] = sum_d Q[row][d]*K[col][d]
        float s_acc[4][4];
#pragma unroll
        for (int i = 0; i < 4; i++)
#pragma unroll
            for (int j = 0; j < 4; j++) s_acc[i][j] = 0.0f;

#pragma unroll 4
        for (int d = 0; d < HD; d++) {
            float4 a = *(const float4*)&Qt[d * QT_STR + ty*4];
            float4 b = *(const float4*)&Kt[d * QT_STR + tx*4];
            float av[4] = {a.x, a.y, a.z, a.w};
            float bv[4] = {b.x, b.y, b.z, b.w};
#pragma unroll
            for (int i = 0; i < 4; i++)
#pragma unroll
                for (int j = 0; j < 4; j++)
                    s_acc[i][j] = fmaf(av[i], bv[j], s_acc[i][j]);
        }

        // scale + causal mask + online softmax (row groups of 16 lanes share a row)
#pragma unroll
        for (int i = 0; i < 4; i++) {
            const int qi = q0 + ty*4 + i;
            float mx = -1e30f;
#pragma unroll
            for (int j = 0; j < 4; j++) {
                float sv = s_acc[i][j] * scale;
                if (k0 + tx*4 + j > qi) sv = -1e30f;
                s_acc[i][j] = sv;
                mx = fmaxf(mx, sv);
            }
#pragma unroll
            for (int off = 8; off >= 1; off >>= 1)
                mx = fmaxf(mx, __shfl_xor_sync(0xffffffffu, mx, off));

            const float mnew = fmaxf(m_i[i], mx);
            const float corr = __expf(m_i[i] - mnew);
            m_i[i] = mnew;

            float pv[4];
            float rs = 0.0f;
#pragma unroll
            for (int j = 0; j < 4; j++) {
                pv[j] = __expf(s_acc[i][j] - mnew);
                rs += pv[j];
            }
#pragma unroll
            for (int off = 8; off >= 1; off >>= 1)
                rs += __shfl_xor_sync(0xffffffffu, rs, off);

            l_i[i] = l_i[i] * corr + rs;
#pragma unroll
            for (int j = 0; j < 8; j++) o_acc[i][j] *= corr;

            *(float4*)&Ps[(ty*4 + i) * PS_STR + tx*4] = make_float4(pv[0], pv[1], pv[2], pv[3]);
        }
        __syncthreads();

        // O += P * V : rows ty*4+i, cols tx*8..+7
#pragma unroll 2
        for (int k = 0; k < BKV; k++) {
            float4 v0 = *(const float4*)&Vs[k * VS_STR + tx*8];
            float4 v1 = *(const float4*)&Vs[k * VS_STR + tx*8 + 4];
#pragma unroll
            for (int i = 0; i < 4; i++) {
                float p = Ps[(ty*4 + i) * PS_STR + k];
                o_acc[i][0] = fmaf(p, v0.x, o_acc[i][0]);
                o_acc[i][1] = fmaf(p, v0.y, o_acc[i][1]);
                o_acc[i][2] = fmaf(p, v0.z, o_acc[i][2]);
                o_acc[i][3] = fmaf(p, v0.w, o_acc[i][3]);
                o_acc[i][4] = fmaf(p, v1.x, o_acc[i][4]);
                o_acc[i][5] = fmaf(p, v1.y, o_acc[i][5]);
                o_acc[i][6] = fmaf(p, v1.z, o_acc[i][6]);
                o_acc[i][7] = fmaf(p, v1.w, o_acc[i][7]);
            }
        }
    }

    // epilogue: normalize and write [s][head*HD + d]
#pragma unroll
    for (int i = 0; i < 4; i++) {
        const float inv = 1.0f / l_i[i];
        float* op = out + (size_t)(q0 + ty*4 + i) * HID + head * HD + tx*8;
        *(float4*)op       = make_float4(o_acc[i][0]*inv, o_acc[i][1]*inv,
                                         o_acc[i][2]*inv, o_acc[i][3]*inv);
        *(float4*)(op + 4) = make_float4(o_acc[i][4]*inv, o_acc[i][5]*inv,
                                         o_acc[i][6]*inv, o_acc[i][7]*inv);
    }
}

// ============================================================================
// Launch: QKV GEMM -> flash attention -> O-proj GEMM
// ============================================================================
extern "C" void kernel_launch(void* const* d_in, const int* in_sizes, int n_in,
                              void* d_out, int out_size) {
    const float* hidden = (const float*)d_in[0];   // [1,2048,5120]
    const float* wpack  = (const float*)d_in[1];   // [15360,5120]
    const float* wo     = (const float*)d_in[2];   // [5120,5120]
    float* out = (float*)d_out;                    // [1,2048,5120]

    float *qkv_ptr = nullptr, *attno_ptr = nullptr;
    cudaGetSymbolAddress((void**)&qkv_ptr, g_qkv);
    cudaGetSymbolAddress((void**)&attno_ptr, g_attno);

    cudaFuncSetAttribute(flash_attn_kernel,
                         cudaFuncAttributeMaxDynamicSharedMemorySize,
                         FLASH_SMEM_BYTES);

    // 1. QKV projection: [2048,15360] = H[2048,5120] * Wpack^T
    dim3 g1(QKV_N / 128, S_LEN / 128);
    gemm_tn_kernel<<<g1, 256>>>(hidden, wpack, qkv_ptr, S_LEN, QKV_N, HID);

    // 2. Causal flash attention over 40 heads
    dim3 g2(S_LEN / BQ, NH);
    flash_attn_kernel<<<g2, 256, FLASH_SMEM_BYTES>>>(qkv_ptr, attno_ptr);

    // 3. Output projection: [2048,5120] = A[2048,5120] * Wo^T
    dim3 g3(HID / 128, S_LEN / 128);
    gemm_tn_kernel<<<g3, 256>>>(attno_ptr, wo, out, S_LEN, HID, HID);
}

// round 3
// speedup vs baseline: 2.4683x; 2.4683x over previous
#include <cuda_runtime.h>
#include <cstdint>
#include <math.h>

#define S_LEN 2048
#define HID   5120
#define NH    40
#define HD    128
#define QKV_N (3*HID)   // 15360

// ---- mma.sync tf32 GEMM tiling ----
#define MT 128
#define NT 128
#define KT 32
#define ROW_STR 36                        // floats per smem row (32 data + 4 pad)
#define STAGE_FLOATS (2*128*ROW_STR)      // A+B one stage = 9216 floats
#define STAGE_BYTES  (STAGE_FLOATS*4)     // 36864
#define GEMM_SMEM_BYTES (2*STAGE_BYTES)   // 73728

// ---- flash-attention tiling ----
#define BQ  64
#define BKV 64
#define QT_STR 68
#define VS_STR 132
#define PS_STR 68
#define FLASH_SMEM_FLOATS (2*HD*QT_STR + BKV*VS_STR + BQ*PS_STR)
#define FLASH_SMEM_BYTES  (FLASH_SMEM_FLOATS*4)   // 120832 bytes

// Scratch (allocation-free rule: __device__ globals)
__device__ float g_qkv[(size_t)S_LEN * QKV_N];
__device__ float g_attno[(size_t)S_LEN * HID];

// ============================================================================
// PTX helpers (arch-stable: ldmatrix + mma.sync, no tcgen05)
// ============================================================================
__device__ __forceinline__ uint32_t smem_u32(const void* p) {
    uint32_t a;
    asm("{ .reg .u64 t; cvta.to.shared.u64 t, %1; cvt.u32.u64 %0, t; }"
        : "=r"(a) : "l"(p));
    return a;
}

__device__ __forceinline__ uint32_t f2tf(float x) {
    uint32_t r;
    asm("cvt.rna.tf32.f32 %0, %1;" : "=r"(r) : "f"(x));
    return r;
}

__device__ __forceinline__ void ldsm4(uint32_t* r, uint32_t a) {
    asm volatile("ldmatrix.sync.aligned.m8n8.x4.shared.b16 {%0,%1,%2,%3}, [%4];"
                 : "=r"(r[0]), "=r"(r[1]), "=r"(r[2]), "=r"(r[3]) : "r"(a));
}

__device__ __forceinline__ void mma_tf32(float* c, const uint32_t* a,
                                         uint32_t b0, uint32_t b1) {
    asm volatile(
        "mma.sync.aligned.m16n8k8.row.col.f32.tf32.tf32.f32 "
        "{%0,%1,%2,%3}, {%4,%5,%6,%7}, {%8,%9}, {%0,%1,%2,%3};"
        : "+f"(c[0]), "+f"(c[1]), "+f"(c[2]), "+f"(c[3])
        : "r"(a[0]), "r"(a[1]), "r"(a[2]), "r"(a[3]), "r"(b0), "r"(b1));
}

// ============================================================================
// tf32 tensor-core GEMM (TN): C[m,n] = sum_k A[m*K+k] * B[n*K+k]
// 128x128 CTA tile, 8 warps (4m x 2n), warp tile 32x64, KT=32 double-buffered.
// ============================================================================
__global__ __launch_bounds__(256, 1)
void gemm_tn_mma(const float* __restrict__ A, const float* __restrict__ B,
                 float* __restrict__ C, int M, int N, int K) {
    extern __shared__ __align__(16) float sm[];
    const uint32_t sbase = smem_u32(sm);

    const int t   = threadIdx.x;
    const int wid = t >> 5;
    const int ln  = t & 31;
    const int m0  = blockIdx.x * MT;
    const int n0  = blockIdx.y * NT;
    const int warp_m0 = (wid >> 1) * 32;
    const int warp_n0 = (wid & 1) * 64;

    // global load geometry: 8 x float4 per thread per k-tile
    const int row_l = t >> 3;          // 0..31
    const int seg   = t & 7;           // 0..7 (16B segments)
    const float* Ag = A + (size_t)(m0 + row_l) * K + seg * 4;
    const float* Bg = B + (size_t)(n0 + row_l) * K + seg * 4;
    const int sts_off = row_l * ROW_STR + seg * 4;   // + 32i*ROW_STR

    // ldmatrix per-lane base addresses (byte offsets into a stage)
    const uint32_t a_lane = ((uint32_t)(warp_m0 + (ln & 15)) * ROW_STR
                             + (((uint32_t)ln >> 4) << 2)) * 4u;
    const uint32_t b_lane = (uint32_t)(128 * ROW_STR * 4)
                          + ((uint32_t)(warp_n0 + (ln & 7) + ((ln & 16) >> 1)) * ROW_STR
                             + (((uint32_t)(ln >> 3) & 1u) << 2)) * 4u;

    float acc[2][8][4];
#pragma unroll
    for (int mi = 0; mi < 2; mi++)
#pragma unroll
        for (int nf = 0; nf < 8; nf++)
#pragma unroll
            for (int r = 0; r < 4; r++) acc[mi][nf][r] = 0.0f;

    const int NKT = K / KT;

    // prologue: stage 0
    {
        float4 a4[4], b4[4];
#pragma unroll
        for (int i = 0; i < 4; i++) {
            a4[i] = *(const float4*)(Ag + (size_t)(32 * i) * K);
            b4[i] = *(const float4*)(Bg + (size_t)(32 * i) * K);
        }
#pragma unroll
        for (int i = 0; i < 4; i++) {
            uint4 ua = make_uint4(f2tf(a4[i].x), f2tf(a4[i].y), f2tf(a4[i].z), f2tf(a4[i].w));
            uint4 ub = make_uint4(f2tf(b4[i].x), f2tf(b4[i].y), f2tf(b4[i].z), f2tf(b4[i].w));
            *(uint4*)(sm + sts_off + 32 * i * ROW_STR) = ua;
            *(uint4*)(sm + 128 * ROW_STR + sts_off + 32 * i * ROW_STR) = ub;
        }
        __syncthreads();
    }

#pragma unroll 1
    for (int kt = 0; kt < NKT; kt++) {
        const bool more = (kt + 1 < NKT);
        float4 na[4], nb[4];
        if (more) {
            const int k1 = (kt + 1) * KT;
#pragma unroll
            for (int i = 0; i < 4; i++) {
                na[i] = *(const float4*)(Ag + (size_t)(32 * i) * K + k1);
                nb[i] = *(const float4*)(Bg + (size_t)(32 * i) * K + k1);
            }
        }

        // compute tile kt from stage kt&1
        const uint32_t so = sbase + (uint32_t)(kt & 1) * STAGE_BYTES;
#pragma unroll
        for (int ks = 0; ks < 4; ks++) {
            uint32_t af[2][4];
            ldsm4(af[0], so + a_lane + ks * 32);
            ldsm4(af[1], so + a_lane + 16 * ROW_STR * 4 + ks * 32);
            uint32_t bf[4][4];
#pragma unroll
            for (int nfp = 0; nfp < 4; nfp++)
                ldsm4(bf[nfp], so + b_lane + nfp * (16 * ROW_STR * 4) + ks * 32);
#pragma unroll
            for (int mi = 0; mi < 2; mi++)
#pragma unroll
                for (int nf = 0; nf < 8; nf++)
                    mma_tf32(acc[mi][nf], af[mi],
                             bf[nf >> 1][(nf & 1) * 2], bf[nf >> 1][(nf & 1) * 2 + 1]);
        }

        if (more) {
            float* dst = sm + ((kt + 1) & 1) * STAGE_FLOATS;
#pragma unroll
            for (int i = 0; i < 4; i++) {
                uint4 ua = make_uint4(f2tf(na[i].x), f2tf(na[i].y), f2tf(na[i].z), f2tf(na[i].w));
                uint4 ub = make_uint4(f2tf(nb[i].x), f2tf(nb[i].y), f2tf(nb[i].z), f2tf(nb[i].w));
                *(uint4*)(dst + sts_off + 32 * i * ROW_STR) = ua;
                *(uint4*)(dst + 128 * ROW_STR + sts_off + 32 * i * ROW_STR) = ub;
            }
            __syncthreads();
        }
    }

    // epilogue: direct global stores (float2 per fragment half)
#pragma unroll
    for (int mi = 0; mi < 2; mi++) {
        const int r0 = m0 + warp_m0 + mi * 16 + (ln >> 2);
#pragma unroll
        for (int nf = 0; nf < 8; nf++) {
            const int cc = n0 + warp_n0 + nf * 8 + (ln & 3) * 2;
            *(float2*)(C + (size_t)r0 * N + cc) =
                make_float2(acc[mi][nf][0], acc[mi][nf][1]);
            *(float2*)(C + (size_t)(r0 + 8) * N + cc) =
                make_float2(acc[mi][nf][2], acc[mi][nf][3]);
        }
    }
}

// ============================================================================
// Flash attention (fp32, causal). Grid (S/BQ, NH), 256 threads. (unchanged)
// ============================================================================
__global__ __launch_bounds__(256, 1)
void flash_attn_kernel(const float* __restrict__ qkv, float* __restrict__ out) {
    extern __shared__ float smf[];
    float* Qt = smf;
    float* Kt = Qt + HD * QT_STR;
    float* Vs = Kt + HD * QT_STR;
    float* Ps = Vs + BKV * VS_STR;

    const int head = blockIdx.y;
    const int qb   = blockIdx.x;
    const int q0   = qb * BQ;
    const int tid  = threadIdx.x;
    const int ty   = tid >> 4;
    const int tx   = tid & 15;
    const int lseg = tid & 31;
    const int lr0  = tid >> 5;

    const float scale = 1.0f / sqrtf((float)HD);

#pragma unroll
    for (int it = 0; it < 8; it++) {
        int q = it * 8 + lr0;
        float4 v = *(const float4*)&qkv[(size_t)(q0 + q) * QKV_N + head * HD + lseg * 4];
        Qt[(lseg*4 + 0) * QT_STR + q] = v.x;
        Qt[(lseg*4 + 1) * QT_STR + q] = v.y;
        Qt[(lseg*4 + 2) * QT_STR + q] = v.z;
        Qt[(lseg*4 + 3) * QT_STR + q] = v.w;
    }

    float m_i[4], l_i[4], o_acc[4][8];
#pragma unroll
    for (int i = 0; i < 4; i++) {
        m_i[i] = -1e30f; l_i[i] = 0.0f;
#pragma unroll
        for (int j = 0; j < 8; j++) o_acc[i][j] = 0.0f;
    }

    for (int kb = 0; kb <= qb; kb++) {
        const int k0 = kb * BKV;

        __syncthreads();

#pragma unroll
        for (int it = 0; it < 8; it++) {
            int kv = it * 8 + lr0;
            const float* kp = &qkv[(size_t)(k0 + kv) * QKV_N +   HID + head * HD + lseg * 4];
            const float* vp = &qkv[(size_t)(k0 + kv) * QKV_N + 2*HID + head * HD + lseg * 4];
            float4 kk = *(const float4*)kp;
            Kt[(lseg*4 + 0) * QT_STR + kv] = kk.x;
            Kt[(lseg*4 + 1) * QT_STR + kv] = kk.y;
            Kt[(lseg*4 + 2) * QT_STR + kv] = kk.z;
            Kt[(lseg*4 + 3) * QT_STR + kv] = kk.w;
            *(float4*)&Vs[kv * VS_STR + lseg * 4] = *(const float4*)vp;
        }
        __syncthreads();

        float s_acc[4][4];
#pragma unroll
        for (int i = 0; i < 4; i++)
#pragma unroll
            for (int j = 0; j < 4; j++) s_acc[i][j] = 0.0f;

#pragma unroll 4
        for (int d = 0; d < HD; d++) {
            float4 a = *(const float4*)&Qt[d * QT_STR + ty*4];
            float4 b = *(const float4*)&Kt[d * QT_STR + tx*4];
            float av[4] = {a.x, a.y, a.z, a.w};
            float bv[4] = {b.x, b.y, b.z, b.w};
#pragma unroll
            for (int i = 0; i < 4; i++)
#pragma unroll
                for (int j = 0; j < 4; j++)
                    s_acc[i][j] = fmaf(av[i], bv[j], s_acc[i][j]);
        }

#pragma unroll
        for (int i = 0; i < 4; i++) {
            const int qi = q0 + ty*4 + i;
            float mx = -1e30f;
#pragma unroll
            for (int j = 0; j < 4; j++) {
                float sv = s_acc[i][j] * scale;
                if (k0 + tx*4 + j > qi) sv = -1e30f;
                s_acc[i][j] = sv;
                mx = fmaxf(mx, sv);
            }
#pragma unroll
            for (int off = 8; off >= 1; off >>= 1)
                mx = fmaxf(mx, __shfl_xor_sync(0xffffffffu, mx, off));

            const float mnew = fmaxf(m_i[i], mx);
            const float corr = __expf(m_i[i] - mnew);
            m_i[i] = mnew;

            float pv[4];
            float rs = 0.0f;
#pragma unroll
            for (int j = 0; j < 4; j++) {
                pv[j] = __expf(s_acc[i][j] - mnew);
                rs += pv[j];
            }
#pragma unroll
            for (int off = 8; off >= 1; off >>= 1)
                rs += __shfl_xor_sync(0xffffffffu, rs, off);

            l_i[i] = l_i[i] * corr + rs;
#pragma unroll
            for (int j = 0; j < 8; j++) o_acc[i][j] *= corr;

            *(float4*)&Ps[(ty*4 + i) * PS_STR + tx*4] = make_float4(pv[0], pv[1], pv[2], pv[3]);
        }
        __syncthreads();

#pragma unroll 2
        for (int k = 0; k < BKV; k++) {
            float4 v0 = *(const float4*)&Vs[k * VS_STR + tx*8];
            float4 v1 = *(const float4*)&Vs[k * VS_STR + tx*8 + 4];
#pragma unroll
            for (int i = 0; i < 4; i++) {
                float p = Ps[(ty*4 + i) * PS_STR + k];
                o_acc[i][0] = fmaf(p, v0.x, o_acc[i][0]);
                o_acc[i][1] = fmaf(p, v0.y, o_acc[i][1]);
                o_acc[i][2] = fmaf(p, v0.z, o_acc[i][2]);
                o_acc[i][3] = fmaf(p, v0.w, o_acc[i][3]);
                o_acc[i][4] = fmaf(p, v1.x, o_acc[i][4]);
                o_acc[i][5] = fmaf(p, v1.y, o_acc[i][5]);
                o_acc[i][6] = fmaf(p, v1.z, o_acc[i][6]);
                o_acc[i][7] = fmaf(p, v1.w, o_acc[i][7]);
            }
        }
    }

#pragma unroll
    for (int i = 0; i < 4; i++) {
        const float inv = 1.0f / l_i[i];
        float* op = out + (size_t)(q0 + ty*4 + i) * HID + head * HD + tx*8;
        *(float4*)op       = make_float4(o_acc[i][0]*inv, o_acc[i][1]*inv,
                                         o_acc[i][2]*inv, o_acc[i][3]*inv);
        *(float4*)(op + 4) = make_float4(o_acc[i][4]*inv, o_acc[i][5]*inv,
                                         o_acc[i][6]*inv, o_acc[i][7]*inv);
    }
}

// ============================================================================
// Launch
// ============================================================================
extern "C" void kernel_launch(void* const* d_in, const int* in_sizes, int n_in,
                              void* d_out, int out_size) {
    const float* hidden = (const float*)d_in[0];
    const float* wpack  = (const float*)d_in[1];
    const float* wo     = (const float*)d_in[2];
    float* out = (float*)d_out;

    float *qkv_ptr = nullptr, *attno_ptr = nullptr;
    cudaGetSymbolAddress((void**)&qkv_ptr, g_qkv);
    cudaGetSymbolAddress((void**)&attno_ptr, g_attno);

    cudaFuncSetAttribute(gemm_tn_mma,
                         cudaFuncAttributeMaxDynamicSharedMemorySize, GEMM_SMEM_BYTES);
    cudaFuncSetAttribute(flash_attn_kernel,
                         cudaFuncAttributeMaxDynamicSharedMemorySize, FLASH_SMEM_BYTES);

    // 1. QKV projection: [2048,15360] = H * Wpack^T
    dim3 g1(S_LEN / MT, QKV_N / NT);
    gemm_tn_mma<<<g1, 256, GEMM_SMEM_BYTES>>>(hidden, wpack, qkv_ptr, S_LEN, QKV_N, HID);

    // 2. Causal flash attention over 40 heads
    dim3 g2(S_LEN / BQ, NH);
    flash_attn_kernel<<<g2, 256, FLASH_SMEM_BYTES>>>(qkv_ptr, attno_ptr);

    // 3. Output projection: [2048,5120] = A * Wo^T
    dim3 g3(S_LEN / MT, HID / NT);
    gemm_tn_mma<<<g3, 256, GEMM_SMEM_BYTES>>>(attno_ptr, wo, out, S_LEN, HID, HID);
}

// round 4
// speedup vs baseline: 4.0018x; 1.6213x over previous
#include <cuda_runtime.h>
#include <cuda_fp16.h>
#include <cstdint>
#include <math.h>

#define S_LEN 2048
#define HID   5120
#define NH    40
#define HD    128
#define QKV_N (3*HID)   // 15360

// ---- fp16 mma GEMM tiling ----
#define MT 128
#define NT 128
#define KT 32
#define BSTR 40                         // halves per smem row (32 data + 8 pad)
#define TILE_BYTES (128*BSTR*2)         // 10240 per operand tile
#define STAGE_SPLIT  (3*TILE_BYTES)     // A + Bhi + Blo
#define STAGE_SINGLE (2*TILE_BYTES)     // A + B
#define GEMM_SMEM_SPLIT  (2*STAGE_SPLIT)    // 61440
#define GEMM_SMEM_SINGLE (2*STAGE_SINGLE)   // 40960

// ---- flash-attention (fp16 tensor) ----
#define BQ 64
#define BKV 64
#define AQS 136                         // halves stride for 128-wide rows
#define ATILE_BYTES (64*AQS*2)          // 17408
#define ASMEM (6*ATILE_BYTES)           // Qh Ql Kh Kl Vh Vl = 104448

// Scratch (allocation-free rule: __device__ globals)
__device__ float g_qkv[(size_t)S_LEN * QKV_N];
__device__ float g_attno[(size_t)S_LEN * HID];

// ============================================================================
// PTX helpers
// ============================================================================
__device__ __forceinline__ uint32_t smem_u32(const void* p) {
    uint32_t a;
    asm("{ .reg .u64 t; cvta.to.shared.u64 t, %1; cvt.u32.u64 %0, t; }"
        : "=r"(a) : "l"(p));
    return a;
}

__device__ __forceinline__ void ldsm4(uint32_t* r, uint32_t a) {
    asm volatile("ldmatrix.sync.aligned.m8n8.x4.shared.b16 {%0,%1,%2,%3}, [%4];"
                 : "=r"(r[0]), "=r"(r[1]), "=r"(r[2]), "=r"(r[3]) : "r"(a));
}
__device__ __forceinline__ void ldsm4t(uint32_t* r, uint32_t a) {
    asm volatile("ldmatrix.sync.aligned.m8n8.x4.trans.shared.b16 {%0,%1,%2,%3}, [%4];"
                 : "=r"(r[0]), "=r"(r[1]), "=r"(r[2]), "=r"(r[3]) : "r"(a));
}

__device__ __forceinline__ void mma16(float* c, const uint32_t* a,
                                      uint32_t b0, uint32_t b1) {
    asm volatile(
        "mma.sync.aligned.m16n8k16.row.col.f32.f16.f16.f32 "
        "{%0,%1,%2,%3}, {%4,%5,%6,%7}, {%8,%9}, {%0,%1,%2,%3};"
        : "+f"(c[0]), "+f"(c[1]), "+f"(c[2]), "+f"(c[3])
        : "r"(a[0]), "r"(a[1]), "r"(a[2]), "r"(a[3]), "r"(b0), "r"(b1));
}

__device__ __forceinline__ uint32_t packh2(float a, float b) {
    __half2 h = __floats2half2_rn(a, b);
    return *reinterpret_cast<uint32_t*>(&h);
}

// split helpers: x = hi + lo (both fp16-representable)
__device__ __forceinline__ void split4(const float4 v, uint2& hi, uint2& lo) {
    __half h0 = __float2half_rn(v.x), h1 = __float2half_rn(v.y);
    __half h2 = __float2half_rn(v.z), h3 = __float2half_rn(v.w);
    hi.x = packh2(v.x, v.y);  // rn-pack == (h0,h1)
    hi.y = packh2(v.z, v.w);
    lo.x = packh2(v.x - __half2float(h0), v.y - __half2float(h1));
    lo.y = packh2(v.z - __half2float(h2), v.w - __half2float(h3));
}
__device__ __forceinline__ uint2 cvt4(const float4 v) {
    uint2 r; r.x = packh2(v.x, v.y); r.y = packh2(v.z, v.w); return r;
}

// ============================================================================
// fp16 tensor-core GEMM (TN): C[m,n] = sum_k A[m*K+k] * B[n*K+k]
// SPLITB: B = B_hi + B_lo (removes weight-rounding error).
// 128x128 CTA tile, 8 warps (4m x 2n), warp 32x64, KT=32 double-buffered.
// ============================================================================
template<bool SPLITB>
__global__ __launch_bounds__(256, 1)
void gemm16_tn(const float* __restrict__ A, const float* __restrict__ B,
               float* __restrict__ C, int M, int N, int K) {
    extern __shared__ __align__(16) char sm[];
    const uint32_t sb = smem_u32(sm);
    const uint32_t stageBytes = SPLITB ? STAGE_SPLIT : STAGE_SINGLE;

    const int t   = threadIdx.x;
    const int wid = t >> 5;
    const int ln  = t & 31;
    const int m0  = blockIdx.x * MT;
    const int n0  = blockIdx.y * NT;
    const int wm  = (wid >> 1) * 32;
    const int wn  = (wid & 1) * 64;

    const int rl  = t >> 3;            // 0..31
    const int seg = t & 7;             // 0..7
    const float* Ag = A + (size_t)(m0 + rl) * K + seg * 4;
    const float* Bg = B + (size_t)(n0 + rl) * K + seg * 4;
    const uint32_t stsOff = (uint32_t)(rl * BSTR + seg * 4) * 2;  // bytes

    // ldmatrix lane addresses (bytes within stage)
    const uint32_t aoff = ((uint32_t)(wm + (ln & 15)) * BSTR + 8u * (ln >> 4)) * 2;
    const uint32_t boff = TILE_BYTES +
        ((uint32_t)(wn + (ln & 7) + 8 * (ln >> 4)) * BSTR + 8u * ((ln >> 3) & 1)) * 2;

    float acc[2][8][4];
#pragma unroll
    for (int mi = 0; mi < 2; mi++)
#pragma unroll
        for (int nf = 0; nf < 8; nf++)
#pragma unroll
            for (int r = 0; r < 4; r++) acc[mi][nf][r] = 0.0f;

    const int NKT = K / KT;

    // ---- prologue: fill stage 0 ----
    {
        float4 a4[4], b4[4];
#pragma unroll
        for (int i = 0; i < 4; i++) {
            a4[i] = *(const float4*)(Ag + (size_t)(32 * i) * K);
            b4[i] = *(const float4*)(Bg + (size_t)(32 * i) * K);
        }
#pragma unroll
        for (int i = 0; i < 4; i++) {
            const uint32_t ro = stsOff + (uint32_t)(32 * i) * BSTR * 2;
            *(uint2*)(sm + ro) = cvt4(a4[i]);
            if (SPLITB) {
                uint2 hi, lo; split4(b4[i], hi, lo);
                *(uint2*)(sm + TILE_BYTES + ro) = hi;
                *(uint2*)(sm + 2 * TILE_BYTES + ro) = lo;
            } else {
                *(uint2*)(sm + TILE_BYTES + ro) = cvt4(b4[i]);
            }
        }
        __syncthreads();
    }

#pragma unroll 1
    for (int kt = 0; kt < NKT; kt++) {
        const bool more = (kt + 1 < NKT);
        float4 na[4], nb[4];
        if (more) {
            const int k1 = (kt + 1) * KT;
#pragma unroll
            for (int i = 0; i < 4; i++) {
                na[i] = *(const float4*)(Ag + (size_t)(32 * i) * K + k1);
                nb[i] = *(const float4*)(Bg + (size_t)(32 * i) * K + k1);
            }
        }

        const uint32_t so = sb + (uint32_t)(kt & 1) * stageBytes;
#pragma unroll
        for (int ks = 0; ks < 2; ks++) {
            const uint32_t ko = ks * 32;   // 16 halves
            uint32_t af[2][4];
            ldsm4(af[0], so + aoff + ko);
            ldsm4(af[1], so + aoff + 16 * BSTR * 2 + ko);
            uint32_t bh[4][4];
#pragma unroll
            for (int p = 0; p < 4; p++)
                ldsm4(bh[p], so + boff + p * (16 * BSTR * 2) + ko);
            uint32_t bl[4][4];
            if (SPLITB) {
#pragma unroll
                for (int p = 0; p < 4; p++)
                    ldsm4(bl[p], so + boff + TILE_BYTES + p * (16 * BSTR * 2) + ko);
            }
#pragma unroll
            for (int mi = 0; mi < 2; mi++)
#pragma unroll
                for (int nf = 0; nf < 8; nf++) {
                    mma16(acc[mi][nf], af[mi],
                          bh[nf >> 1][(nf & 1) * 2], bh[nf >> 1][(nf & 1) * 2 + 1]);
                    if (SPLITB)
                        mma16(acc[mi][nf], af[mi],
                              bl[nf >> 1][(nf & 1) * 2], bl[nf >> 1][(nf & 1) * 2 + 1]);
                }
        }

        if (more) {
            char* dst = sm + ((kt + 1) & 1) * stageBytes;
#pragma unroll
            for (int i = 0; i < 4; i++) {
                const uint32_t ro = stsOff + (uint32_t)(32 * i) * BSTR * 2;
                *(uint2*)(dst + ro) = cvt4(na[i]);
                if (SPLITB) {
                    uint2 hi, lo; split4(nb[i], hi, lo);
                    *(uint2*)(dst + TILE_BYTES + ro) = hi;
                    *(uint2*)(dst + 2 * TILE_BYTES + ro) = lo;
                } else {
                    *(uint2*)(dst + TILE_BYTES + ro) = cvt4(nb[i]);
                }
            }
            __syncthreads();
        }
    }

    // epilogue
#pragma unroll
    for (int mi = 0; mi < 2; mi++) {
        const int r0 = m0 + wm + mi * 16 + (ln >> 2);
#pragma unroll
        for (int nf = 0; nf < 8; nf++) {
            const int cc = n0 + wn + nf * 8 + (ln & 3) * 2;
            *(float2*)(C + (size_t)r0 * N + cc) = make_float2(acc[mi][nf][0], acc[mi][nf][1]);
            *(float2*)(C + (size_t)(r0 + 8) * N + cc) = make_float2(acc[mi][nf][2], acc[mi][nf][3]);
        }
    }
}

// ============================================================================
// Flash attention, fp16 tensor cores, causal. Grid (S/64, NH), 128 threads.
// S = Qh*Kh + Qh*Kl + Ql*Kh (compensated). O += P*(Vh+Vlo).
// Each warp owns 16 Q rows x full 64 KV cols x full 128 d (register P).
// ============================================================================
__global__ __launch_bounds__(128, 1)
void flash16_kernel(const float* __restrict__ qkv, float* __restrict__ out) {
    extern __shared__ __align__(16) char sm[];
    const uint32_t sb = smem_u32(sm);
    char* Qh = sm;
    char* Ql = Qh + ATILE_BYTES;
    char* Kh = Ql + ATILE_BYTES;
    char* Kl = Kh + ATILE_BYTES;
    char* Vh = Kl + ATILE_BYTES;
    char* Vl = Vh + ATILE_BYTES;
    const uint32_t uQh = sb, uQl = uQh + ATILE_BYTES, uKh = uQl + ATILE_BYTES,
                   uKl = uKh + ATILE_BYTES, uVh = uKl + ATILE_BYTES, uVl = uVh + ATILE_BYTES;

    const int head = blockIdx.y;
    const int qb   = blockIdx.x;
    const int q0   = qb * BQ;
    const int t    = threadIdx.x;
    const int w    = t >> 5;
    const int ln   = t & 31;
    const int m0w  = w * 16;
    const float scale = 0.08838834764831845f;   // 1/sqrt(128)

    // ---- load Q (rows 16w..16w+15), hi/lo split ----
#pragma unroll 4
    for (int rr = 0; rr < 16; rr++) {
        const int r = m0w + rr;
        float4 v = *(const float4*)&qkv[(size_t)(q0 + r) * QKV_N + head * HD + ln * 4];
        uint2 hi, lo; split4(v, hi, lo);
        const uint32_t ro = (uint32_t)(r * AQS + ln * 4) * 2;
        *(uint2*)(Qh + ro) = hi;
        *(uint2*)(Ql + ro) = lo;
    }

    float m_i[2] = {-1e30f, -1e30f};
    float l_i[2] = {0.0f, 0.0f};
    float o[16][4];
#pragma unroll
    for (int d = 0; d < 16; d++)
#pragma unroll
        for (int r = 0; r < 4; r++) o[d][r] = 0.0f;

    // lane addresses
    const uint32_t aQ = ((uint32_t)(m0w + (ln & 15)) * AQS + 8u * (ln >> 4)) * 2;
    const uint32_t bK = ((uint32_t)((ln & 7) + 8 * (ln >> 4)) * AQS + 8u * ((ln >> 3) & 1)) * 2;
    const uint32_t bV = ((uint32_t)((ln & 7) + 8 * ((ln >> 3) & 1)) * AQS + 8u * (ln >> 4)) * 2;

    const int r1g = q0 + m0w + (ln >> 2);
    const int r2g = r1g + 8;

    for (int kb = 0; kb <= qb; kb++) {
        const int k0 = kb * BKV;

        __syncthreads();
        // ---- load K, V tiles (rows 16w..16w+15 of this KV block) ----
#pragma unroll 4
        for (int rr = 0; rr < 16; rr++) {
            const int r = m0w + rr;
            float4 kv4 = *(const float4*)&qkv[(size_t)(k0 + r) * QKV_N + HID + head * HD + ln * 4];
            float4 vv4 = *(const float4*)&qkv[(size_t)(k0 + r) * QKV_N + 2 * HID + head * HD + ln * 4];
            uint2 hi, lo;
            const uint32_t ro = (uint32_t)(r * AQS + ln * 4) * 2;
            split4(kv4, hi, lo);
            *(uint2*)(Kh + ro) = hi;
            *(uint2*)(Kl + ro) = lo;
            split4(vv4, hi, lo);
            *(uint2*)(Vh + ro) = hi;
            *(uint2*)(Vl + ro) = lo;
        }
        __syncthreads();

        // ---- S = Q K^T (compensated) ----
        float s[8][4];
#pragma unroll
        for (int nf = 0; nf < 8; nf++)
#pragma unroll
            for (int r = 0; r < 4; r++) s[nf][r] = 0.0f;

#pragma unroll
        for (int ks = 0; ks < 8; ks++) {
            const uint32_t ko = ks * 32;
            uint32_t qh[4], ql[4];
            ldsm4(qh, uQh + aQ + ko);
            ldsm4(ql, uQl + aQ + ko);
            uint32_t kh[4][4], kl[4][4];
#pragma unroll
            for (int p = 0; p < 4; p++) {
                ldsm4(kh[p], uKh + bK + p * (16 * AQS * 2) + ko);
                ldsm4(kl[p], uKl + bK + p * (16 * AQS * 2) + ko);
            }
#pragma unroll
            for (int nf = 0; nf < 8; nf++) {
                const uint32_t h0 = kh[nf >> 1][(nf & 1) * 2], h1 = kh[nf >> 1][(nf & 1) * 2 + 1];
                const uint32_t l0 = kl[nf >> 1][(nf & 1) * 2], l1 = kl[nf >> 1][(nf & 1) * 2 + 1];
                mma16(s[nf], qh, h0, h1);
                mma16(s[nf], qh, l0, l1);
                mma16(s[nf], ql, h0, h1);
            }
        }

        // ---- online softmax (rows r1g, r2g) ----
        float mx1 = -1e30f, mx2 = -1e30f;
#pragma unroll
        for (int nf = 0; nf < 8; nf++) {
            float v0 = s[nf][0] * scale, v1 = s[nf][1] * scale;
            float v2 = s[nf][2] * scale, v3 = s[nf][3] * scale;
            if (kb == qb) {
                const int cb = k0 + nf * 8 + 2 * (ln & 3);
                if (cb     > r1g) v0 = -1e30f;
                if (cb + 1 > r1g) v1 = -1e30f;
                if (cb     > r2g) v2 = -1e30f;
                if (cb + 1 > r2g) v3 = -1e30f;
            }
            s[nf][0] = v0; s[nf][1] = v1; s[nf][2] = v2; s[nf][3] = v3;
            mx1 = fmaxf(mx1, fmaxf(v0, v1));
            mx2 = fmaxf(mx2, fmaxf(v2, v3));
        }
        mx1 = fmaxf(mx1, __shfl_xor_sync(0xffffffffu, mx1, 1));
        mx1 = fmaxf(mx1, __shfl_xor_sync(0xffffffffu, mx1, 2));
        mx2 = fmaxf(mx2, __shfl_xor_sync(0xffffffffu, mx2, 1));
        mx2 = fmaxf(mx2, __shfl_xor_sync(0xffffffffu, mx2, 2));

        const float mn1 = fmaxf(m_i[0], mx1);
        const float mn2 = fmaxf(m_i[1], mx2);
        const float corr1 = __expf(m_i[0] - mn1);
        const float corr2 = __expf(m_i[1] - mn2);
        m_i[0] = mn1; m_i[1] = mn2;

        float rs1 = 0.0f, rs2 = 0.0f;
#pragma unroll
        for (int nf = 0; nf < 8; nf++) {
            float p0 = __expf(s[nf][0] - mn1);
            float p1 = __expf(s[nf][1] - mn1);
            float p2 = __expf(s[nf][2] - mn2);
            float p3 = __expf(s[nf][3] - mn2);
            rs1 += p0 + p1; rs2 += p2 + p3;
            s[nf][0] = p0; s[nf][1] = p1; s[nf][2] = p2; s[nf][3] = p3;
        }
        rs1 += __shfl_xor_sync(0xffffffffu, rs1, 1);
        rs1 += __shfl_xor_sync(0xffffffffu, rs1, 2);
        rs2 += __shfl_xor_sync(0xffffffffu, rs2, 1);
        rs2 += __shfl_xor_sync(0xffffffffu, rs2, 2);
        l_i[0] = l_i[0] * corr1 + rs1;
        l_i[1] = l_i[1] * corr2 + rs2;

#pragma unroll
        for (int d = 0; d < 16; d++) {
            o[d][0] *= corr1; o[d][1] *= corr1;
            o[d][2] *= corr2; o[d][3] *= corr2;
        }

        // ---- P repack (C-frags -> A-frags, in registers) ----
        uint32_t pa[4][4];
#pragma unroll
        for (int tk = 0; tk < 4; tk++) {
            pa[tk][0] = packh2(s[2 * tk][0],     s[2 * tk][1]);
            pa[tk][1] = packh2(s[2 * tk][2],     s[2 * tk][3]);
            pa[tk][2] = packh2(s[2 * tk + 1][0], s[2 * tk + 1][1]);
            pa[tk][3] = packh2(s[2 * tk + 1][2], s[2 * tk + 1][3]);
        }

        // ---- O += P V (V split: P*Vh + P*Vl) ----
#pragma unroll
        for (int tk = 0; tk < 4; tk++) {
            const uint32_t rowo = (uint32_t)(16 * tk) * AQS * 2;
#pragma unroll
            for (int p = 0; p < 8; p++) {
                const uint32_t vo = rowo + bV + (uint32_t)(16 * p) * 2;
                uint32_t vh[4], vl[4];
                ldsm4t(vh, uVh + vo);
                ldsm4t(vl, uVl + vo);
                mma16(o[2 * p],     pa[tk], vh[0], vh[1]);
                mma16(o[2 * p],     pa[tk], vl[0], vl[1]);
                mma16(o[2 * p + 1], pa[tk], vh[2], vh[3]);
                mma16(o[2 * p + 1], pa[tk], vl[2], vl[3]);
            }
        }
    }

    // ---- epilogue ----
    const float inv1 = 1.0f / l_i[0];
    const float inv2 = 1.0f / l_i[1];
#pragma unroll
    for (int d = 0; d < 16; d++) {
        const int cc = head * HD + d * 8 + 2 * (ln & 3);
        *(float2*)(out + (size_t)r1g * HID + cc) = make_float2(o[d][0] * inv1, o[d][1] * inv1);
        *(float2*)(out + (size_t)r2g * HID + cc) = make_float2(o[d][2] * inv2, o[d][3] * inv2);
    }
}

// ============================================================================
// Launch
// ============================================================================
extern "C" void kernel_launch(void* const* d_in, const int* in_sizes, int n_in,
                              void* d_out, int out_size) {
    const float* hidden = (const float*)d_in[0];
    const float* wpack  = (const float*)d_in[1];
    const float* wo     = (const float*)d_in[2];
    float* out = (float*)d_out;

    float *qkv_ptr = nullptr, *attno_ptr = nullptr;
    cudaGetSymbolAddress((void**)&qkv_ptr, g_qkv);
    cudaGetSymbolAddress((void**)&attno_ptr, g_attno);

    cudaFuncSetAttribute(gemm16_tn<true>,
                         cudaFuncAttributeMaxDynamicSharedMemorySize, GEMM_SMEM_SPLIT);
    cudaFuncSetAttribute(gemm16_tn<false>,
                         cudaFuncAttributeMaxDynamicSharedMemorySize, GEMM_SMEM_SINGLE);
    cudaFuncSetAttribute(flash16_kernel,
                         cudaFuncAttributeMaxDynamicSharedMemorySize, ASMEM);

    // 1. QKV projection (split-B for precision): [2048,15360] = H * Wpack^T
    dim3 g1(S_LEN / MT, QKV_N / NT);
    gemm16_tn<true><<<g1, 256, GEMM_SMEM_SPLIT>>>(hidden, wpack, qkv_ptr, S_LEN, QKV_N, HID);

    // 2. Causal flash attention (fp16 tensor, compensated QK)
    dim3 g2(S_LEN / BQ, NH);
    flash16_kernel<<<g2, 128, ASMEM>>>(qkv_ptr, attno_ptr);

    // 3. Output projection (single fp16): [2048,5120] = A * Wo^T
    dim3 g3(S_LEN / MT, HID / NT);
    gemm16_tn<false><<<g3, 256, GEMM_SMEM_SINGLE>>>(attno_ptr, wo, out, S_LEN, HID, HID);
}

// round 5
// speedup vs baseline: 4.3039x; 1.0755x over previous
#include <cuda_runtime.h>
#include <cuda_fp16.h>
#include <cstdint>
#include <math.h>

#define S_LEN 2048
#define HID   5120
#define NH    40
#define HD    128
#define QKV_N (3*HID)   // 15360

// ---- fp16 mma GEMM tiling ----
#define MT 128
#define NT 128
#define KT 32
#define BSTR 40                         // halves per smem row (32 data + 8 pad)
#define TILE_BYTES (128*BSTR*2)         // 10240 per operand tile
#define STAGE_SPLIT  (3*TILE_BYTES)     // A + Bhi + Blo = 30720
#define STAGE_SINGLE (2*TILE_BYTES)     // A + B        = 20480
#define GEMM_SMEM_SPLIT  (4*STAGE_SPLIT)    // 122880
#define GEMM_SMEM_SINGLE (4*STAGE_SINGLE)   // 81920

// ---- flash-attention (fp16 tensor) ----
#define BQ 64
#define BKV 64
#define AQS 136                         // halves stride for 128-wide rows
#define ATILE_BYTES (64*AQS*2)          // 17408
#define ASMEM (6*ATILE_BYTES)           // Qh Ql Kh Kl Vh Vl = 104448

// Scratch (allocation-free rule: __device__ globals)
__device__ float  g_qkv[(size_t)S_LEN * QKV_N];        // fp32 QKV (attention input)
__device__ __half g_h16[(size_t)S_LEN * HID];          // hidden fp16
__device__ __half g_wp_hi[(size_t)QKV_N * HID];        // Wpack hi
__device__ __half g_wp_lo[(size_t)QKV_N * HID];        // Wpack lo
__device__ __half g_wo16[(size_t)HID * HID];           // Wo fp16
__device__ __half g_attno16[(size_t)S_LEN * HID];      // attention out fp16

// ============================================================================
// PTX helpers
// ============================================================================
__device__ __forceinline__ uint32_t smem_u32(const void* p) {
    uint32_t a;
    asm("{ .reg .u64 t; cvta.to.shared.u64 t, %1; cvt.u32.u64 %0, t; }"
        : "=r"(a) : "l"(p));
    return a;
}

__device__ __forceinline__ void ldsm4(uint32_t* r, uint32_t a) {
    asm volatile("ldmatrix.sync.aligned.m8n8.x4.shared.b16 {%0,%1,%2,%3}, [%4];"
                 : "=r"(r[0]), "=r"(r[1]), "=r"(r[2]), "=r"(r[3]) : "r"(a));
}
__device__ __forceinline__ void ldsm4t(uint32_t* r, uint32_t a) {
    asm volatile("ldmatrix.sync.aligned.m8n8.x4.trans.shared.b16 {%0,%1,%2,%3}, [%4];"
                 : "=r"(r[0]), "=r"(r[1]), "=r"(r[2]), "=r"(r[3]) : "r"(a));
}

__device__ __forceinline__ void mma16(float* c, const uint32_t* a,
                                      uint32_t b0, uint32_t b1) {
    asm volatile(
        "mma.sync.aligned.m16n8k16.row.col.f32.f16.f16.f32 "
        "{%0,%1,%2,%3}, {%4,%5,%6,%7}, {%8,%9}, {%0,%1,%2,%3};"
        : "+f"(c[0]), "+f"(c[1]), "+f"(c[2]), "+f"(c[3])
        : "r"(a[0]), "r"(a[1]), "r"(a[2]), "r"(a[3]), "r"(b0), "r"(b1));
}

__device__ __forceinline__ uint32_t packh2(float a, float b) {
    __half2 h = __floats2half2_rn(a, b);
    return *reinterpret_cast<uint32_t*>(&h);
}

__device__ __forceinline__ void split4(const float4 v, uint2& hi, uint2& lo) {
    __half h0 = __float2half_rn(v.x), h1 = __float2half_rn(v.y);
    __half h2 = __float2half_rn(v.z), h3 = __float2half_rn(v.w);
    hi.x = packh2(v.x, v.y);
    hi.y = packh2(v.z, v.w);
    lo.x = packh2(v.x - __half2float(h0), v.y - __half2float(h1));
    lo.y = packh2(v.z - __half2float(h2), v.w - __half2float(h3));
}
__device__ __forceinline__ uint2 cvt4(const float4 v) {
    uint2 r; r.x = packh2(v.x, v.y); r.y = packh2(v.z, v.w); return r;
}

__device__ __forceinline__ void cpa16(uint32_t dst, const void* src) {
    asm volatile("cp.async.cg.shared.global [%0], [%1], 16;"
                 :: "r"(dst), "l"(src) : "memory");
}
__device__ __forceinline__ void cp_commit() {
    asm volatile("cp.async.commit_group;" ::: "memory");
}
template<int N> __device__ __forceinline__ void cp_wait() {
    asm volatile("cp.async.wait_group %0;" :: "n"(N) : "memory");
}

// ============================================================================
// Pre-conversion kernels
// ============================================================================
__global__ void cvt_split_kernel(const float4* __restrict__ in,
                                 uint2* __restrict__ hi, uint2* __restrict__ lo,
                                 int n4) {
    for (int i = blockIdx.x * blockDim.x + threadIdx.x; i < n4;
         i += gridDim.x * blockDim.x) {
        uint2 h, l; split4(in[i], h, l);
        hi[i] = h; lo[i] = l;
    }
}
__global__ void cvt_one_kernel(const float4* __restrict__ in,
                               uint2* __restrict__ out, int n4) {
    for (int i = blockIdx.x * blockDim.x + threadIdx.x; i < n4;
         i += gridDim.x * blockDim.x)
        out[i] = cvt4(in[i]);
}

// ============================================================================
// fp16 tensor GEMM (TN), pre-converted operands, 4-stage cp.async pipeline.
// C[m,n] = sum_k A[m,k] * (Bh[n,k] + (SPLITB ? Bl[n,k] : 0))
// 128x128 CTA tile, 8 warps (4m x 2n), KT=32.
// ============================================================================
template<bool SPLITB>
__global__ __launch_bounds__(256, 1)
void gemm16p(const __half* __restrict__ A, const __half* __restrict__ Bh,
             const __half* __restrict__ Bl, float* __restrict__ C,
             int M, int N, int K) {
    extern __shared__ __align__(16) char sm[];
    const uint32_t sb = smem_u32(sm);
    const uint32_t stageBytes = SPLITB ? STAGE_SPLIT : STAGE_SINGLE;

    const int t   = threadIdx.x;
    const int wid = t >> 5;
    const int ln  = t & 31;
    const int m0  = blockIdx.x * MT;
    const int n0  = blockIdx.y * NT;
    const int wm  = (wid >> 1) * 32;
    const int wn  = (wid & 1) * 64;

    // cp.async geometry: 512 chunks (16B) per tile, 2 per thread
    const int r0 = t >> 2;             // 0..63
    const int sg = t & 3;              // 0..3
    const __half* Ag0 = A  + (size_t)(m0 + r0) * K + sg * 8;
    const __half* Ag1 = Ag0 + (size_t)64 * K;
    const __half* Bh0 = Bh + (size_t)(n0 + r0) * K + sg * 8;
    const __half* Bh1 = Bh0 + (size_t)64 * K;
    const __half* Bl0 = SPLITB ? (Bl + (size_t)(n0 + r0) * K + sg * 8) : (const __half*)0;
    const __half* Bl1 = SPLITB ? (Bl0 + (size_t)64 * K) : (const __half*)0;
    const uint32_t d0 = (uint32_t)r0 * (BSTR * 2) + sg * 16;
    const uint32_t d1 = d0 + 64 * (BSTR * 2);

    // ldmatrix lane addresses (bytes within stage)
    const uint32_t aoff = ((uint32_t)(wm + (ln & 15)) * BSTR + 8u * (ln >> 4)) * 2;
    const uint32_t boff = TILE_BYTES +
        ((uint32_t)(wn + (ln & 7) + 8 * (ln >> 4)) * BSTR + 8u * ((ln >> 3) & 1)) * 2;

    float acc[2][8][4];
#pragma unroll
    for (int mi = 0; mi < 2; mi++)
#pragma unroll
        for (int nf = 0; nf < 8; nf++)
#pragma unroll
            for (int r = 0; r < 4; r++) acc[mi][nf][r] = 0.0f;

    const int NKT = K / KT;   // 160

    auto issue = [&](int st, int kt) {
        const uint32_t base = sb + (uint32_t)st * stageBytes;
        const size_t ko = (size_t)kt * KT;
        cpa16(base + d0, Ag0 + ko);
        cpa16(base + d1, Ag1 + ko);
        cpa16(base + TILE_BYTES + d0, Bh0 + ko);
        cpa16(base + TILE_BYTES + d1, Bh1 + ko);
        if (SPLITB) {
            cpa16(base + 2 * TILE_BYTES + d0, Bl0 + ko);
            cpa16(base + 2 * TILE_BYTES + d1, Bl1 + ko);
        }
    };

    issue(0, 0); cp_commit();
    issue(1, 1); cp_commit();
    issue(2, 2); cp_commit();

#pragma unroll 1
    for (int kt = 0; kt < NKT; kt++) {
        cp_wait<2>();
        __syncthreads();

        const uint32_t so = sb + (uint32_t)(kt & 3) * stageBytes;
#pragma unroll
        for (int ks = 0; ks < 2; ks++) {
            const uint32_t ko = ks * 32;   // 16 halves
            uint32_t af[2][4];
            ldsm4(af[0], so + aoff + ko);
            ldsm4(af[1], so + aoff + 16 * BSTR * 2 + ko);
            uint32_t bh[4][4];
#pragma unroll
            for (int p = 0; p < 4; p++)
                ldsm4(bh[p], so + boff + p * (16 * BSTR * 2) + ko);
            uint32_t bl[4][4];
            if (SPLITB) {
#pragma unroll
                for (int p = 0; p < 4; p++)
                    ldsm4(bl[p], so + boff + TILE_BYTES + p * (16 * BSTR * 2) + ko);
            }
#pragma unroll
            for (int mi = 0; mi < 2; mi++)
#pragma unroll
                for (int nf = 0; nf < 8; nf++) {
                    mma16(acc[mi][nf], af[mi],
                          bh[nf >> 1][(nf & 1) * 2], bh[nf >> 1][(nf & 1) * 2 + 1]);
                    if (SPLITB)
                        mma16(acc[mi][nf], af[mi],
                              bl[nf >> 1][(nf & 1) * 2], bl[nf >> 1][(nf & 1) * 2 + 1]);
                }
        }

        const int nk = kt + 3;
        if (nk < NKT) issue(nk & 3, nk);
        cp_commit();
    }

    // epilogue: direct f32 stores
#pragma unroll
    for (int mi = 0; mi < 2; mi++) {
        const int r = m0 + wm + mi * 16 + (ln >> 2);
#pragma unroll
        for (int nf = 0; nf < 8; nf++) {
            const int cc = n0 + wn + nf * 8 + (ln & 3) * 2;
            *(float2*)(C + (size_t)r * N + cc) = make_float2(acc[mi][nf][0], acc[mi][nf][1]);
            *(float2*)(C + (size_t)(r + 8) * N + cc) = make_float2(acc[mi][nf][2], acc[mi][nf][3]);
        }
    }
}

// ============================================================================
// Flash attention, fp16 tensor cores, causal. Grid (S/64, NH), 128 threads,
// 2 CTAs/SM. Compensated S = QhKh + QhKl + QlKh; O += P(Vh+Vl). fp16 output.
// ============================================================================
__global__ __launch_bounds__(128, 2)
void flash16_kernel(const float* __restrict__ qkv, __half* __restrict__ out) {
    extern __shared__ __align__(16) char sm[];
    const uint32_t sb = smem_u32(sm);
    char* Qh = sm;
    char* Ql = Qh + ATILE_BYTES;
    char* Kh = Ql + ATILE_BYTES;
    char* Kl = Kh + ATILE_BYTES;
    char* Vh = Kl + ATILE_BYTES;
    char* Vl = Vh + ATILE_BYTES;
    const uint32_t uQh = sb, uQl = uQh + ATILE_BYTES, uKh = uQl + ATILE_BYTES,
                   uKl = uKh + ATILE_BYTES, uVh = uKl + ATILE_BYTES, uVl = uVh + ATILE_BYTES;

    const int head = blockIdx.y;
    const int qb   = blockIdx.x;
    const int q0   = qb * BQ;
    const int t    = threadIdx.x;
    const int w    = t >> 5;
    const int ln   = t & 31;
    const int m0w  = w * 16;
    const float scale = 0.08838834764831845f;   // 1/sqrt(128)

#pragma unroll 4
    for (int rr = 0; rr < 16; rr++) {
        const int r = m0w + rr;
        float4 v = *(const float4*)&qkv[(size_t)(q0 + r) * QKV_N + head * HD + ln * 4];
        uint2 hi, lo; split4(v, hi, lo);
        const uint32_t ro = (uint32_t)(r * AQS + ln * 4) * 2;
        *(uint2*)(Qh + ro) = hi;
        *(uint2*)(Ql + ro) = lo;
    }

    float m_i[2] = {-1e30f, -1e30f};
    float l_i[2] = {0.0f, 0.0f};
    float o[16][4];
#pragma unroll
    for (int d = 0; d < 16; d++)
#pragma unroll
        for (int r = 0; r < 4; r++) o[d][r] = 0.0f;

    const uint32_t aQ = ((uint32_t)(m0w + (ln & 15)) * AQS + 8u * (ln >> 4)) * 2;
    const uint32_t bK = ((uint32_t)((ln & 7) + 8 * (ln >> 4)) * AQS + 8u * ((ln >> 3) & 1)) * 2;
    const uint32_t bV = ((uint32_t)((ln & 7) + 8 * ((ln >> 3) & 1)) * AQS + 8u * (ln >> 4)) * 2;

    const int r1g = q0 + m0w + (ln >> 2);
    const int r2g = r1g + 8;

    for (int kb = 0; kb <= qb; kb++) {
        const int k0 = kb * BKV;

        __syncthreads();
#pragma unroll 4
        for (int rr = 0; rr < 16; rr++) {
            const int r = m0w + rr;
            float4 kv4 = *(const float4*)&qkv[(size_t)(k0 + r) * QKV_N + HID + head * HD + ln * 4];
            float4 vv4 = *(const float4*)&qkv[(size_t)(k0 + r) * QKV_N + 2 * HID + head * HD + ln * 4];
            uint2 hi, lo;
            const uint32_t ro = (uint32_t)(r * AQS + ln * 4) * 2;
            split4(kv4, hi, lo);
            *(uint2*)(Kh + ro) = hi;
            *(uint2*)(Kl + ro) = lo;
            split4(vv4, hi, lo);
            *(uint2*)(Vh + ro) = hi;
            *(uint2*)(Vl + ro) = lo;
        }
        __syncthreads();

        float s[8][4];
#pragma unroll
        for (int nf = 0; nf < 8; nf++)
#pragma unroll
            for (int r = 0; r < 4; r++) s[nf][r] = 0.0f;

#pragma unroll
        for (int ks = 0; ks < 8; ks++) {
            const uint32_t ko = ks * 32;
            uint32_t qh[4], ql[4];
            ldsm4(qh, uQh + aQ + ko);
            ldsm4(ql, uQl + aQ + ko);
            uint32_t kh[4][4], kl[4][4];
#pragma unroll
            for (int p = 0; p < 4; p++) {
                ldsm4(kh[p], uKh + bK + p * (16 * AQS * 2) + ko);
                ldsm4(kl[p], uKl + bK + p * (16 * AQS * 2) + ko);
            }
#pragma unroll
            for (int nf = 0; nf < 8; nf++) {
                const uint32_t h0 = kh[nf >> 1][(nf & 1) * 2], h1 = kh[nf >> 1][(nf & 1) * 2 + 1];
                const uint32_t l0 = kl[nf >> 1][(nf & 1) * 2], l1 = kl[nf >> 1][(nf & 1) * 2 + 1];
                mma16(s[nf], qh, h0, h1);
                mma16(s[nf], qh, l0, l1);
                mma16(s[nf], ql, h0, h1);
            }
        }

        float mx1 = -1e30f, mx2 = -1e30f;
#pragma unroll
        for (int nf = 0; nf < 8; nf++) {
            float v0 = s[nf][0] * scale, v1 = s[nf][1] * scale;
            float v2 = s[nf][2] * scale, v3 = s[nf][3] * scale;
            if (kb == qb) {
                const int cb = k0 + nf * 8 + 2 * (ln & 3);
                if (cb     > r1g) v0 = -1e30f;
                if (cb + 1 > r1g) v1 = -1e30f;
                if (cb     > r2g) v2 = -1e30f;
                if (cb + 1 > r2g) v3 = -1e30f;
            }
            s[nf][0] = v0; s[nf][1] = v1; s[nf][2] = v2; s[nf][3] = v3;
            mx1 = fmaxf(mx1, fmaxf(v0, v1));
            mx2 = fmaxf(mx2, fmaxf(v2, v3));
        }
        mx1 = fmaxf(mx1, __shfl_xor_sync(0xffffffffu, mx1, 1));
        mx1 = fmaxf(mx1, __shfl_xor_sync(0xffffffffu, mx1, 2));
        mx2 = fmaxf(mx2, __shfl_xor_sync(0xffffffffu, mx2, 1));
        mx2 = fmaxf(mx2, __shfl_xor_sync(0xffffffffu, mx2, 2));

        const float mn1 = fmaxf(m_i[0], mx1);
        const float mn2 = fmaxf(m_i[1], mx2);
        const float corr1 = __expf(m_i[0] - mn1);
        const float corr2 = __expf(m_i[1] - mn2);
        m_i[0] = mn1; m_i[1] = mn2;

        float rs1 = 0.0f, rs2 = 0.0f;
#pragma unroll
        for (int nf = 0; nf < 8; nf++) {
            float p0 = __expf(s[nf][0] - mn1);
            float p1 = __expf(s[nf][1] - mn1);
            float p2 = __expf(s[nf][2] - mn2);
            float p3 = __expf(s[nf][3] - mn2);
            rs1 += p0 + p1; rs2 += p2 + p3;
            s[nf][0] = p0; s[nf][1] = p1; s[nf][2] = p2; s[nf][3] = p3;
        }
        rs1 += __shfl_xor_sync(0xffffffffu, rs1, 1);
        rs1 += __shfl_xor_sync(0xffffffffu, rs1, 2);
        rs2 += __shfl_xor_sync(0xffffffffu, rs2, 1);
        rs2 += __shfl_xor_sync(0xffffffffu, rs2, 2);
        l_i[0] = l_i[0] * corr1 + rs1;
        l_i[1] = l_i[1] * corr2 + rs2;

#pragma unroll
        for (int d = 0; d < 16; d++) {
            o[d][0] *= corr1; o[d][1] *= corr1;
            o[d][2] *= corr2; o[d][3] *= corr2;
        }

        uint32_t pa[4][4];
#pragma unroll
        for (int tk = 0; tk < 4; tk++) {
            pa[tk][0] = packh2(s[2 * tk][0],     s[2 * tk][1]);
            pa[tk][1] = packh2(s[2 * tk][2],     s[2 * tk][3]);
            pa[tk][2] = packh2(s[2 * tk + 1][0], s[2 * tk + 1][1]);
            pa[tk][3] = packh2(s[2 * tk + 1][2], s[2 * tk + 1][3]);
        }

#pragma unroll
        for (int tk = 0; tk < 4; tk++) {
            const uint32_t rowo = (uint32_t)(16 * tk) * AQS * 2;
#pragma unroll
            for (int p = 0; p < 8; p++) {
                const uint32_t vo = rowo + bV + (uint32_t)(16 * p) * 2;
                uint32_t vh[4], vl[4];
                ldsm4t(vh, uVh + vo);
                ldsm4t(vl, uVl + vo);
                mma16(o[2 * p],     pa[tk], vh[0], vh[1]);
                mma16(o[2 * p],     pa[tk], vl[0], vl[1]);
                mma16(o[2 * p + 1], pa[tk], vh[2], vh[3]);
                mma16(o[2 * p + 1], pa[tk], vl[2], vl[3]);
            }
        }
    }

    // epilogue: fp16 output (O-proj consumes fp16)
    const float inv1 = 1.0f / l_i[0];
    const float inv2 = 1.0f / l_i[1];
#pragma unroll
    for (int d = 0; d < 16; d++) {
        const int cc = head * HD + d * 8 + 2 * (ln & 3);
        *(__half2*)(out + (size_t)r1g * HID + cc) =
            __floats2half2_rn(o[d][0] * inv1, o[d][1] * inv1);
        *(__half2*)(out + (size_t)r2g * HID + cc) =
            __floats2half2_rn(o[d][2] * inv2, o[d][3] * inv2);
    }
}

// ============================================================================
// Launch
// ============================================================================
extern "C" void kernel_launch(void* const* d_in, const int* in_sizes, int n_in,
                              void* d_out, int out_size) {
    const float* hidden = (const float*)d_in[0];
    const float* wpack  = (const float*)d_in[1];
    const float* wo     = (const float*)d_in[2];
    float* out = (float*)d_out;

    float *qkv_ptr = nullptr;
    __half *h16, *wph, *wpl, *wo16, *at16;
    cudaGetSymbolAddress((void**)&qkv_ptr, g_qkv);
    cudaGetSymbolAddress((void**)&h16,  g_h16);
    cudaGetSymbolAddress((void**)&wph,  g_wp_hi);
    cudaGetSymbolAddress((void**)&wpl,  g_wp_lo);
    cudaGetSymbolAddress((void**)&wo16, g_wo16);
    cudaGetSymbolAddress((void**)&at16, g_attno16);

    cudaFuncSetAttribute(gemm16p<true>,
                         cudaFuncAttributeMaxDynamicSharedMemorySize, GEMM_SMEM_SPLIT);
    cudaFuncSetAttribute(gemm16p<false>,
                         cudaFuncAttributeMaxDynamicSharedMemorySize, GEMM_SMEM_SINGLE);
    cudaFuncSetAttribute(flash16_kernel,
                         cudaFuncAttributeMaxDynamicSharedMemorySize, ASMEM);

    // 0. pre-conversions
    cvt_one_kernel<<<4096, 256>>>((const float4*)hidden, (uint2*)h16,
                                  (int)((size_t)S_LEN * HID / 4));
    cvt_split_kernel<<<8192, 256>>>((const float4*)wpack, (uint2*)wph, (uint2*)wpl,
                                    (int)((size_t)QKV_N * HID / 4));
    cvt_one_kernel<<<8192, 256>>>((const float4*)wo, (uint2*)wo16,
                                  (int)((size_t)HID * HID / 4));

    // 1. QKV projection (split-B): [2048,15360] = H * Wpack^T
    dim3 g1(S_LEN / MT, QKV_N / NT);
    gemm16p<true><<<g1, 256, GEMM_SMEM_SPLIT>>>(h16, wph, wpl, qkv_ptr,
                                                S_LEN, QKV_N, HID);

    // 2. Causal flash attention (fp16 tensor, compensated QK) -> fp16
    dim3 g2(S_LEN / BQ, NH);
    flash16_kernel<<<g2, 128, ASMEM>>>(qkv_ptr, at16);

    // 3. Output projection (single fp16): [2048,5120] = A * Wo^T
    dim3 g3(S_LEN / MT, HID / NT);
    gemm16p<false><<<g3, 256, GEMM_SMEM_SINGLE>>>(at16, wo16, nullptr, out,
                                                  S_LEN, HID, HID);
}

// round 6
// speedup vs baseline: 4.9682x; 1.1543x over previous
#include <cuda_runtime.h>
#include <cuda_fp16.h>
#include <cstdint>
#include <math.h>

#define S_LEN 2048
#define HID   5120
#define NH    40
#define HD    128
#define QKV_N (3*HID)   // 15360

// ---- fp16 mma GEMM tiling ----
#define MT 128
#define NT 128
#define KT 32
#define BSTR 40                         // halves per smem row (32 data + 8 pad)
#define TILE_BYTES (128*BSTR*2)         // 10240 per operand tile
#define STAGE_SPLIT  (3*TILE_BYTES)     // A + Bhi + Blo = 30720
#define STAGE_SINGLE (2*TILE_BYTES)     // A + B        = 20480
#define STAGES_SPLIT  3
#define STAGES_SINGLE 4
#define GEMM_SMEM_SPLIT  (STAGES_SPLIT*STAGE_SPLIT)     // 92160  (x2 CTA = 184320)
#define GEMM_SMEM_SINGLE (STAGES_SINGLE*STAGE_SINGLE)   // 81920  (x2 CTA = 163840)

// ---- flash-attention (fp16 tensor) ----
#define BQ 64
#define BKV 64
#define AQS 136                         // halves stride for 128-wide rows
#define ATILE_BYTES (64*AQS*2)          // 17408
#define ASMEM (6*ATILE_BYTES)           // Qh Ql Kh Kl Vh Vl = 104448 (x2 CTA ok)

// Scratch (allocation-free rule: __device__ globals)
__device__ __half g_qkvh[(size_t)S_LEN * QKV_N];       // QKV hi fp16
__device__ __half g_qkvl[(size_t)S_LEN * QKV_N];       // QKV lo fp16
__device__ __half g_h16[(size_t)S_LEN * HID];          // hidden fp16
__device__ __half g_wp_hi[(size_t)QKV_N * HID];        // Wpack hi
__device__ __half g_wp_lo[(size_t)QKV_N * HID];        // Wpack lo
__device__ __half g_wo16[(size_t)HID * HID];           // Wo fp16
__device__ __half g_attno16[(size_t)S_LEN * HID];      // attention out fp16

// ============================================================================
// PTX helpers
// ============================================================================
__device__ __forceinline__ uint32_t smem_u32(const void* p) {
    uint32_t a;
    asm("{ .reg .u64 t; cvta.to.shared.u64 t, %1; cvt.u32.u64 %0, t; }"
        : "=r"(a) : "l"(p));
    return a;
}

__device__ __forceinline__ void ldsm4(uint32_t* r, uint32_t a) {
    asm volatile("ldmatrix.sync.aligned.m8n8.x4.shared.b16 {%0,%1,%2,%3}, [%4];"
                 : "=r"(r[0]), "=r"(r[1]), "=r"(r[2]), "=r"(r[3]) : "r"(a));
}
__device__ __forceinline__ void ldsm4t(uint32_t* r, uint32_t a) {
    asm volatile("ldmatrix.sync.aligned.m8n8.x4.trans.shared.b16 {%0,%1,%2,%3}, [%4];"
                 : "=r"(r[0]), "=r"(r[1]), "=r"(r[2]), "=r"(r[3]) : "r"(a));
}

__device__ __forceinline__ void mma16(float* c, const uint32_t* a,
                                      uint32_t b0, uint32_t b1) {
    asm volatile(
        "mma.sync.aligned.m16n8k16.row.col.f32.f16.f16.f32 "
        "{%0,%1,%2,%3}, {%4,%5,%6,%7}, {%8,%9}, {%0,%1,%2,%3};"
        : "+f"(c[0]), "+f"(c[1]), "+f"(c[2]), "+f"(c[3])
        : "r"(a[0]), "r"(a[1]), "r"(a[2]), "r"(a[3]), "r"(b0), "r"(b1));
}

__device__ __forceinline__ uint32_t packh2(float a, float b) {
    __half2 h = __floats2half2_rn(a, b);
    return *reinterpret_cast<uint32_t*>(&h);
}

__device__ __forceinline__ void split4(const float4 v, uint2& hi, uint2& lo) {
    __half h0 = __float2half_rn(v.x), h1 = __float2half_rn(v.y);
    __half h2 = __float2half_rn(v.z), h3 = __float2half_rn(v.w);
    hi.x = packh2(v.x, v.y);
    hi.y = packh2(v.z, v.w);
    lo.x = packh2(v.x - __half2float(h0), v.y - __half2float(h1));
    lo.y = packh2(v.z - __half2float(h2), v.w - __half2float(h3));
}
__device__ __forceinline__ uint2 cvt4(const float4 v) {
    uint2 r; r.x = packh2(v.x, v.y); r.y = packh2(v.z, v.w); return r;
}

__device__ __forceinline__ void cpa16(uint32_t dst, const void* src) {
    asm volatile("cp.async.cg.shared.global [%0], [%1], 16;"
                 :: "r"(dst), "l"(src) : "memory");
}
__device__ __forceinline__ void cp_commit() {
    asm volatile("cp.async.commit_group;" ::: "memory");
}
template<int N> __device__ __forceinline__ void cp_wait() {
    asm volatile("cp.async.wait_group %0;" :: "n"(N) : "memory");
}

// ============================================================================
// Pre-conversion kernels
// ============================================================================
__global__ void cvt_split_kernel(const float4* __restrict__ in,
                                 uint2* __restrict__ hi, uint2* __restrict__ lo,
                                 int n4) {
    for (int i = blockIdx.x * blockDim.x + threadIdx.x; i < n4;
         i += gridDim.x * blockDim.x) {
        uint2 h, l; split4(in[i], h, l);
        hi[i] = h; lo[i] = l;
    }
}
__global__ void cvt_one_kernel(const float4* __restrict__ in,
                               uint2* __restrict__ out, int n4) {
    for (int i = blockIdx.x * blockDim.x + threadIdx.x; i < n4;
         i += gridDim.x * blockDim.x)
        out[i] = cvt4(in[i]);
}

// ============================================================================
// fp16 tensor GEMM (TN), cp.async pipeline, 2 CTAs/SM.
// SPLITB:   B = Bh + Bl (compensated weights)
// SPLITOUT: write hi/lo fp16 split of the fp32 accumulator (QKV path);
//           otherwise write fp32 to Cf.
// ============================================================================
template<bool SPLITB, bool SPLITOUT>
__global__ __launch_bounds__(256, 2)
void gemm16p(const __half* __restrict__ A, const __half* __restrict__ Bh,
             const __half* __restrict__ Bl, float* __restrict__ Cf,
             __half* __restrict__ Chi, __half* __restrict__ Clo,
             int M, int N, int K) {
    extern __shared__ __align__(16) char sm[];
    const uint32_t sb = smem_u32(sm);
    constexpr uint32_t stageBytes = SPLITB ? STAGE_SPLIT : STAGE_SINGLE;
    constexpr int STAGES = SPLITB ? STAGES_SPLIT : STAGES_SINGLE;

    const int t   = threadIdx.x;
    const int wid = t >> 5;
    const int ln  = t & 31;
    const int m0  = blockIdx.x * MT;
    const int n0  = blockIdx.y * NT;
    const int wm  = (wid >> 1) * 32;
    const int wn  = (wid & 1) * 64;

    const int r0 = t >> 2;             // 0..63
    const int sg = t & 3;              // 0..3
    const __half* Ag0 = A  + (size_t)(m0 + r0) * K + sg * 8;
    const __half* Ag1 = Ag0 + (size_t)64 * K;
    const __half* Bh0 = Bh + (size_t)(n0 + r0) * K + sg * 8;
    const __half* Bh1 = Bh0 + (size_t)64 * K;
    const __half* Bl0 = SPLITB ? (Bl + (size_t)(n0 + r0) * K + sg * 8) : (const __half*)0;
    const __half* Bl1 = SPLITB ? (Bl0 + (size_t)64 * K) : (const __half*)0;
    const uint32_t d0 = (uint32_t)r0 * (BSTR * 2) + sg * 16;
    const uint32_t d1 = d0 + 64 * (BSTR * 2);

    const uint32_t aoff = ((uint32_t)(wm + (ln & 15)) * BSTR + 8u * (ln >> 4)) * 2;
    const uint32_t boff = TILE_BYTES +
        ((uint32_t)(wn + (ln & 7) + 8 * (ln >> 4)) * BSTR + 8u * ((ln >> 3) & 1)) * 2;

    float acc[2][8][4];
#pragma unroll
    for (int mi = 0; mi < 2; mi++)
#pragma unroll
        for (int nf = 0; nf < 8; nf++)
#pragma unroll
            for (int r = 0; r < 4; r++) acc[mi][nf][r] = 0.0f;

    const int NKT = K / KT;   // 160

    auto issue = [&](int st, int kt) {
        const uint32_t base = sb + (uint32_t)st * stageBytes;
        const size_t ko = (size_t)kt * KT;
        cpa16(base + d0, Ag0 + ko);
        cpa16(base + d1, Ag1 + ko);
        cpa16(base + TILE_BYTES + d0, Bh0 + ko);
        cpa16(base + TILE_BYTES + d1, Bh1 + ko);
        if (SPLITB) {
            cpa16(base + 2 * TILE_BYTES + d0, Bl0 + ko);
            cpa16(base + 2 * TILE_BYTES + d1, Bl1 + ko);
        }
    };

#pragma unroll
    for (int s = 0; s < STAGES - 1; s++) { issue(s, s); cp_commit(); }

#pragma unroll 1
    for (int kt = 0; kt < NKT; kt++) {
        cp_wait<STAGES - 2>();
        __syncthreads();

        const uint32_t so = sb + (uint32_t)(kt % STAGES) * stageBytes;
#pragma unroll
        for (int ks = 0; ks < 2; ks++) {
            const uint32_t ko = ks * 32;   // 16 halves
            uint32_t af[2][4];
            ldsm4(af[0], so + aoff + ko);
            ldsm4(af[1], so + aoff + 16 * BSTR * 2 + ko);
            uint32_t bh[4][4];
#pragma unroll
            for (int p = 0; p < 4; p++)
                ldsm4(bh[p], so + boff + p * (16 * BSTR * 2) + ko);
            uint32_t bl[4][4];
            if (SPLITB) {
#pragma unroll
                for (int p = 0; p < 4; p++)
                    ldsm4(bl[p], so + boff + TILE_BYTES + p * (16 * BSTR * 2) + ko);
            }
#pragma unroll
            for (int mi = 0; mi < 2; mi++)
#pragma unroll
                for (int nf = 0; nf < 8; nf++) {
                    mma16(acc[mi][nf], af[mi],
                          bh[nf >> 1][(nf & 1) * 2], bh[nf >> 1][(nf & 1) * 2 + 1]);
                    if (SPLITB)
                        mma16(acc[mi][nf], af[mi],
                              bl[nf >> 1][(nf & 1) * 2], bl[nf >> 1][(nf & 1) * 2 + 1]);
                }
        }

        const int nk = kt + STAGES - 1;
        if (nk < NKT) issue(nk % STAGES, nk);
        cp_commit();
    }

    // epilogue
#pragma unroll
    for (int mi = 0; mi < 2; mi++) {
        const int r = m0 + wm + mi * 16 + (ln >> 2);
#pragma unroll
        for (int nf = 0; nf < 8; nf++) {
            const int cc = n0 + wn + nf * 8 + (ln & 3) * 2;
            if (SPLITOUT) {
#pragma unroll
                for (int hh = 0; hh < 2; hh++) {
                    const float v0 = acc[mi][nf][2 * hh], v1 = acc[mi][nf][2 * hh + 1];
                    const __half h0 = __float2half_rn(v0), h1 = __float2half_rn(v1);
                    const size_t off = (size_t)(r + 8 * hh) * N + cc;
                    *(uint32_t*)(Chi + off) = packh2(v0, v1);
                    *(uint32_t*)(Clo + off) =
                        packh2(v0 - __half2float(h0), v1 - __half2float(h1));
                }
            } else {
                *(float2*)(Cf + (size_t)r * N + cc) =
                    make_float2(acc[mi][nf][0], acc[mi][nf][1]);
                *(float2*)(Cf + (size_t)(r + 8) * N + cc) =
                    make_float2(acc[mi][nf][2], acc[mi][nf][3]);
            }
        }
    }
}

// ============================================================================
// Flash attention, fp16 tensor cores, causal. Grid (S/64, NH), 128 threads,
// 2 CTAs/SM. Pre-split hi/lo QKV loaded via cp.async (no conversion math).
// S = QhKh + QhKl + QlKh; O += P(Vh+Vl). fp16 output.
// ============================================================================
__global__ __launch_bounds__(128, 2)
void flash16_kernel(const __half* __restrict__ qh, const __half* __restrict__ ql,
                    __half* __restrict__ out) {
    extern __shared__ __align__(16) char sm[];
    const uint32_t sb = smem_u32(sm);
    const uint32_t uQh = sb, uQl = uQh + ATILE_BYTES, uKh = uQl + ATILE_BYTES,
                   uKl = uKh + ATILE_BYTES, uVh = uKl + ATILE_BYTES, uVl = uVh + ATILE_BYTES;

    const int head = blockIdx.y;
    const int qb   = blockIdx.x;
    const int q0   = qb * BQ;
    const int t    = threadIdx.x;
    const int w    = t >> 5;
    const int ln   = t & 31;
    const int m0w  = w * 16;
    const float scale = 0.08838834764831845f;   // 1/sqrt(128)

    // per-thread load geometry: row pair + 16B segment
    const int lrr = ln >> 4;           // 0..1
    const int seg = ln & 15;           // 0..15
    const uint32_t sdst = (uint32_t)seg * 16;   // byte offset within row

    // ---- load Q (rows 16w..16w+15) hi/lo via cp.async ----
#pragma unroll
    for (int rr = 0; rr < 8; rr++) {
        const int r = m0w + rr * 2 + lrr;
        const size_t go = (size_t)(q0 + r) * QKV_N + head * HD + seg * 8;
        const uint32_t ro = (uint32_t)r * (AQS * 2) + sdst;
        cpa16(uQh + ro, qh + go);
        cpa16(uQl + ro, ql + go);
    }
    cp_commit();

    float m_i[2] = {-1e30f, -1e30f};
    float l_i[2] = {0.0f, 0.0f};
    float o[16][4];
#pragma unroll
    for (int d = 0; d < 16; d++)
#pragma unroll
        for (int r = 0; r < 4; r++) o[d][r] = 0.0f;

    const uint32_t aQ = ((uint32_t)(m0w + (ln & 15)) * AQS + 8u * (ln >> 4)) * 2;
    const uint32_t bK = ((uint32_t)((ln & 7) + 8 * (ln >> 4)) * AQS + 8u * ((ln >> 3) & 1)) * 2;
    const uint32_t bV = ((uint32_t)((ln & 7) + 8 * ((ln >> 3) & 1)) * AQS + 8u * (ln >> 4)) * 2;

    const int r1g = q0 + m0w + (ln >> 2);
    const int r2g = r1g + 8;

    for (int kb = 0; kb <= qb; kb++) {
        const int k0 = kb * BKV;

        __syncthreads();   // prior-iteration consumers of K/V done
        // ---- load K,V (rows 16w..16w+15) hi/lo via cp.async ----
#pragma unroll
        for (int rr = 0; rr < 8; rr++) {
            const int r = m0w + rr * 2 + lrr;
            const size_t gk = (size_t)(k0 + r) * QKV_N + HID + head * HD + seg * 8;
            const size_t gv = gk + HID;
            const uint32_t ro = (uint32_t)r * (AQS * 2) + sdst;
            cpa16(uKh + ro, qh + gk);
            cpa16(uKl + ro, ql + gk);
            cpa16(uVh + ro, qh + gv);
            cpa16(uVl + ro, ql + gv);
        }
        cp_commit();
        cp_wait<0>();
        __syncthreads();

        // ---- S = Q K^T (compensated) ----
        float s[8][4];
#pragma unroll
        for (int nf = 0; nf < 8; nf++)
#pragma unroll
            for (int r = 0; r < 4; r++) s[nf][r] = 0.0f;

#pragma unroll
        for (int ks = 0; ks < 8; ks++) {
            const uint32_t ko = ks * 32;
            uint32_t qhf[4], qlf[4];
            ldsm4(qhf, uQh + aQ + ko);
            ldsm4(qlf, uQl + aQ + ko);
            uint32_t kh[4][4], kl[4][4];
#pragma unroll
            for (int p = 0; p < 4; p++) {
                ldsm4(kh[p], uKh + bK + p * (16 * AQS * 2) + ko);
                ldsm4(kl[p], uKl + bK + p * (16 * AQS * 2) + ko);
            }
#pragma unroll
            for (int nf = 0; nf < 8; nf++) {
                const uint32_t h0 = kh[nf >> 1][(nf & 1) * 2], h1 = kh[nf >> 1][(nf & 1) * 2 + 1];
                const uint32_t l0 = kl[nf >> 1][(nf & 1) * 2], l1 = kl[nf >> 1][(nf & 1) * 2 + 1];
                mma16(s[nf], qhf, h0, h1);
                mma16(s[nf], qhf, l0, l1);
                mma16(s[nf], qlf, h0, h1);
            }
        }

        // ---- online softmax ----
        float mx1 = -1e30f, mx2 = -1e30f;
#pragma unroll
        for (int nf = 0; nf < 8; nf++) {
            float v0 = s[nf][0] * scale, v1 = s[nf][1] * scale;
            float v2 = s[nf][2] * scale, v3 = s[nf][3] * scale;
            if (kb == qb) {
                const int cb = k0 + nf * 8 + 2 * (ln & 3);
                if (cb     > r1g) v0 = -1e30f;
                if (cb + 1 > r1g) v1 = -1e30f;
                if (cb     > r2g) v2 = -1e30f;
                if (cb + 1 > r2g) v3 = -1e30f;
            }
            s[nf][0] = v0; s[nf][1] = v1; s[nf][2] = v2; s[nf][3] = v3;
            mx1 = fmaxf(mx1, fmaxf(v0, v1));
            mx2 = fmaxf(mx2, fmaxf(v2, v3));
        }
        mx1 = fmaxf(mx1, __shfl_xor_sync(0xffffffffu, mx1, 1));
        mx1 = fmaxf(mx1, __shfl_xor_sync(0xffffffffu, mx1, 2));
        mx2 = fmaxf(mx2, __shfl_xor_sync(0xffffffffu, mx2, 1));
        mx2 = fmaxf(mx2, __shfl_xor_sync(0xffffffffu, mx2, 2));

        const float mn1 = fmaxf(m_i[0], mx1);
        const float mn2 = fmaxf(m_i[1], mx2);
        const float corr1 = __expf(m_i[0] - mn1);
        const float corr2 = __expf(m_i[1] - mn2);
        m_i[0] = mn1; m_i[1] = mn2;

        float rs1 = 0.0f, rs2 = 0.0f;
#pragma unroll
        for (int nf = 0; nf < 8; nf++) {
            float p0 = __expf(s[nf][0] - mn1);
            float p1 = __expf(s[nf][1] - mn1);
            float p2 = __expf(s[nf][2] - mn2);
            float p3 = __expf(s[nf][3] - mn2);
            rs1 += p0 + p1; rs2 += p2 + p3;
            s[nf][0] = p0; s[nf][1] = p1; s[nf][2] = p2; s[nf][3] = p3;
        }
        rs1 += __shfl_xor_sync(0xffffffffu, rs1, 1);
        rs1 += __shfl_xor_sync(0xffffffffu, rs1, 2);
        rs2 += __shfl_xor_sync(0xffffffffu, rs2, 1);
        rs2 += __shfl_xor_sync(0xffffffffu, rs2, 2);
        l_i[0] = l_i[0] * corr1 + rs1;
        l_i[1] = l_i[1] * corr2 + rs2;

#pragma unroll
        for (int d = 0; d < 16; d++) {
            o[d][0] *= corr1; o[d][1] *= corr1;
            o[d][2] *= corr2; o[d][3] *= corr2;
        }

        // ---- P repack (C-frags -> A-frags, registers) ----
        uint32_t pa[4][4];
#pragma unroll
        for (int tk = 0; tk < 4; tk++) {
            pa[tk][0] = packh2(s[2 * tk][0],     s[2 * tk][1]);
            pa[tk][1] = packh2(s[2 * tk][2],     s[2 * tk][3]);
            pa[tk][2] = packh2(s[2 * tk + 1][0], s[2 * tk + 1][1]);
            pa[tk][3] = packh2(s[2 * tk + 1][2], s[2 * tk + 1][3]);
        }

        // ---- O += P V (V split) ----
#pragma unroll
        for (int tk = 0; tk < 4; tk++) {
            const uint32_t rowo = (uint32_t)(16 * tk) * AQS * 2;
#pragma unroll
            for (int p = 0; p < 8; p++) {
                const uint32_t vo = rowo + bV + (uint32_t)(16 * p) * 2;
                uint32_t vh[4], vl[4];
                ldsm4t(vh, uVh + vo);
                ldsm4t(vl, uVl + vo);
                mma16(o[2 * p],     pa[tk], vh[0], vh[1]);
                mma16(o[2 * p],     pa[tk], vl[0], vl[1]);
                mma16(o[2 * p + 1], pa[tk], vh[2], vh[3]);
                mma16(o[2 * p + 1], pa[tk], vl[2], vl[3]);
            }
        }
    }

    // epilogue: fp16 output (O-proj consumes fp16)
    const float inv1 = 1.0f / l_i[0];
    const float inv2 = 1.0f / l_i[1];
#pragma unroll
    for (int d = 0; d < 16; d++) {
        const int cc = head * HD + d * 8 + 2 * (ln & 3);
        *(__half2*)(out + (size_t)r1g * HID + cc) =
            __floats2half2_rn(o[d][0] * inv1, o[d][1] * inv1);
        *(__half2*)(out + (size_t)r2g * HID + cc) =
            __floats2half2_rn(o[d][2] * inv2, o[d][3] * inv2);
    }
}

// ============================================================================
// Launch
// ============================================================================
extern "C" void kernel_launch(void* const* d_in, const int* in_sizes, int n_in,
                              void* d_out, int out_size) {
    const float* hidden = (const float*)d_in[0];
    const float* wpack  = (const float*)d_in[1];
    const float* wo     = (const float*)d_in[2];
    float* out = (float*)d_out;

    __half *qkvh, *qkvl, *h16, *wph, *wpl, *wo16, *at16;
    cudaGetSymbolAddress((void**)&qkvh, g_qkvh);
    cudaGetSymbolAddress((void**)&qkvl, g_qkvl);
    cudaGetSymbolAddress((void**)&h16,  g_h16);
    cudaGetSymbolAddress((void**)&wph,  g_wp_hi);
    cudaGetSymbolAddress((void**)&wpl,  g_wp_lo);
    cudaGetSymbolAddress((void**)&wo16, g_wo16);
    cudaGetSymbolAddress((void**)&at16, g_attno16);

    cudaFuncSetAttribute((const void*)gemm16p<true, true>,
                         cudaFuncAttributeMaxDynamicSharedMemorySize, GEMM_SMEM_SPLIT);
    cudaFuncSetAttribute((const void*)gemm16p<false, false>,
                         cudaFuncAttributeMaxDynamicSharedMemorySize, GEMM_SMEM_SINGLE);
    cudaFuncSetAttribute((const void*)flash16_kernel,
                         cudaFuncAttributeMaxDynamicSharedMemorySize, ASMEM);

    // 0. pre-conversions
    cvt_one_kernel<<<4096, 256>>>((const float4*)hidden, (uint2*)h16,
                                  (int)((size_t)S_LEN * HID / 4));
    cvt_split_kernel<<<8192, 256>>>((const float4*)wpack, (uint2*)wph, (uint2*)wpl,
                                    (int)((size_t)QKV_N * HID / 4));
    cvt_one_kernel<<<8192, 256>>>((const float4*)wo, (uint2*)wo16,
                                  (int)((size_t)HID * HID / 4));

    // 1. QKV projection (split-B, split-out): writes hi/lo fp16 QKV
    dim3 g1(S_LEN / MT, QKV_N / NT);
    gemm16p<true, true><<<g1, 256, GEMM_SMEM_SPLIT>>>(
        h16, wph, wpl, nullptr, qkvh, qkvl, S_LEN, QKV_N, HID);

    // 2. Causal flash attention (fp16 tensor, compensated QK) -> fp16
    dim3 g2(S_LEN / BQ, NH);
    flash16_kernel<<<g2, 128, ASMEM>>>(qkvh, qkvl, at16);

    // 3. Output projection (single fp16) -> fp32 out
    dim3 g3(S_LEN / MT, HID / NT);
    gemm16p<false, false><<<g3, 256, GEMM_SMEM_SINGLE>>>(
        at16, wo16, nullptr, out, nullptr, nullptr, S_LEN, HID, HID);
}

// round 7
// speedup vs baseline: 5.3892x; 1.0847x over previous
#include <cuda_runtime.h>
#include <cuda_fp16.h>
#include <cstdint>
#include <math.h>

#define S_LEN 2048
#define HID   5120
#define NH    40
#define HD    128
#define QKV_N (3*HID)   // 15360

// ---- fp16 mma GEMM tiling ----
#define MT 128
#define NT 128
#define KT 32
#define BSTR 40                         // halves per smem row (32 data + 8 pad)
#define TILE_BYTES (128*BSTR*2)         // 10240 per operand tile
#define STAGE_SPLIT  (3*TILE_BYTES)     // A + Bhi + Blo = 30720
#define STAGE_SINGLE (2*TILE_BYTES)     // A + B        = 20480
#define STAGES_SPLIT  3
#define STAGES_SINGLE 4
#define GEMM_SMEM_SPLIT  (STAGES_SPLIT*STAGE_SPLIT)     // 92160
#define GEMM_SMEM_SINGLE (STAGES_SINGLE*STAGE_SINGLE)   // 81920

// ---- flash-attention (fp16 tensor, BQ=128) ----
#define BQ 128
#define BKV 64
#define AQS 136                          // halves stride for 128-wide rows
#define KV_TILE (BKV*AQS*2)              // 17408 (64-row tile)
#define Q_TILE  (BQ*AQS*2)               // 34816 (128-row tile)
#define KVBUF   (3*KV_TILE)              // Kh,Kl,Vh = 52224
#define FSMEM   (2*Q_TILE + 2*KVBUF)     // 174080

// Scratch (allocation-free rule: __device__ globals)
__device__ __half g_qkvh[(size_t)S_LEN * QKV_N];       // QKV hi fp16
__device__ __half g_qkvl[(size_t)S_LEN * QKV_N];       // QKV lo fp16 (Q,K only used)
__device__ __half g_h16[(size_t)S_LEN * HID];          // hidden fp16
__device__ __half g_wp_hi[(size_t)QKV_N * HID];        // Wpack hi (V rows: plain fp16)
__device__ __half g_wp_lo[(size_t)QKV_N * HID];        // Wpack lo (Q,K rows only)
__device__ __half g_wo16[(size_t)HID * HID];           // Wo fp16
__device__ __half g_attno16[(size_t)S_LEN * HID];      // attention out fp16

// ============================================================================
// PTX helpers
// ============================================================================
__device__ __forceinline__ uint32_t smem_u32(const void* p) {
    uint32_t a;
    asm("{ .reg .u64 t; cvta.to.shared.u64 t, %1; cvt.u32.u64 %0, t; }"
        : "=r"(a) : "l"(p));
    return a;
}

__device__ __forceinline__ void ldsm4(uint32_t* r, uint32_t a) {
    asm volatile("ldmatrix.sync.aligned.m8n8.x4.shared.b16 {%0,%1,%2,%3}, [%4];"
                 : "=r"(r[0]), "=r"(r[1]), "=r"(r[2]), "=r"(r[3]) : "r"(a));
}
__device__ __forceinline__ void ldsm4t(uint32_t* r, uint32_t a) {
    asm volatile("ldmatrix.sync.aligned.m8n8.x4.trans.shared.b16 {%0,%1,%2,%3}, [%4];"
                 : "=r"(r[0]), "=r"(r[1]), "=r"(r[2]), "=r"(r[3]) : "r"(a));
}

__device__ __forceinline__ void mma16(float* c, const uint32_t* a,
                                      uint32_t b0, uint32_t b1) {
    asm volatile(
        "mma.sync.aligned.m16n8k16.row.col.f32.f16.f16.f32 "
        "{%0,%1,%2,%3}, {%4,%5,%6,%7}, {%8,%9}, {%0,%1,%2,%3};"
        : "+f"(c[0]), "+f"(c[1]), "+f"(c[2]), "+f"(c[3])
        : "r"(a[0]), "r"(a[1]), "r"(a[2]), "r"(a[3]), "r"(b0), "r"(b1));
}

__device__ __forceinline__ uint32_t packh2(float a, float b) {
    __half2 h = __floats2half2_rn(a, b);
    return *reinterpret_cast<uint32_t*>(&h);
}

__device__ __forceinline__ void split4(const float4 v, uint2& hi, uint2& lo) {
    __half h0 = __float2half_rn(v.x), h1 = __float2half_rn(v.y);
    __half h2 = __float2half_rn(v.z), h3 = __float2half_rn(v.w);
    hi.x = packh2(v.x, v.y);
    hi.y = packh2(v.z, v.w);
    lo.x = packh2(v.x - __half2float(h0), v.y - __half2float(h1));
    lo.y = packh2(v.z - __half2float(h2), v.w - __half2float(h3));
}
__device__ __forceinline__ uint2 cvt4(const float4 v) {
    uint2 r; r.x = packh2(v.x, v.y); r.y = packh2(v.z, v.w); return r;
}

__device__ __forceinline__ void cpa16(uint32_t dst, const void* src) {
    asm volatile("cp.async.cg.shared.global [%0], [%1], 16;"
                 :: "r"(dst), "l"(src) : "memory");
}
__device__ __forceinline__ void cp_commit() {
    asm volatile("cp.async.commit_group;" ::: "memory");
}
template<int N> __device__ __forceinline__ void cp_wait() {
    asm volatile("cp.async.wait_group %0;" :: "n"(N) : "memory");
}

// ============================================================================
// Pre-conversion kernels
// ============================================================================
__global__ void cvt_split_kernel(const float4* __restrict__ in,
                                 uint2* __restrict__ hi, uint2* __restrict__ lo,
                                 int n4) {
    for (int i = blockIdx.x * blockDim.x + threadIdx.x; i < n4;
         i += gridDim.x * blockDim.x) {
        uint2 h, l; split4(in[i], h, l);
        hi[i] = h; lo[i] = l;
    }
}
__global__ void cvt_one_kernel(const float4* __restrict__ in,
                               uint2* __restrict__ out, int n4) {
    for (int i = blockIdx.x * blockDim.x + threadIdx.x; i < n4;
         i += gridDim.x * blockDim.x)
        out[i] = cvt4(in[i]);
}

// ============================================================================
// fp16 tensor GEMM (TN), cp.async pipeline, 2 CTAs/SM.
// SPLITB: B = Bh + Bl for tiles with n0 < 2*HID (Q,K); V tiles plain fp16.
// SPLITOUT: write hi/lo fp16 split of the fp32 accumulator (lo for Q,K only).
// ============================================================================
template<bool SPLITB, bool SPLITOUT>
__global__ __launch_bounds__(256, 2)
void gemm16p(const __half* __restrict__ A, const __half* __restrict__ Bh,
             const __half* __restrict__ Bl, float* __restrict__ Cf,
             __half* __restrict__ Chi, __half* __restrict__ Clo,
             int M, int N, int K) {
    extern __shared__ __align__(16) char sm[];
    const uint32_t sb = smem_u32(sm);
    constexpr uint32_t stageBytes = SPLITB ? STAGE_SPLIT : STAGE_SINGLE;
    constexpr int STAGES = SPLITB ? STAGES_SPLIT : STAGES_SINGLE;

    const int t   = threadIdx.x;
    const int wid = t >> 5;
    const int ln  = t & 31;
    const int m0  = blockIdx.x * MT;
    const int n0  = blockIdx.y * NT;
    const int wm  = (wid >> 1) * 32;
    const int wn  = (wid & 1) * 64;
    const bool useBl = SPLITB && (n0 < 2 * HID);   // Q,K tiles only

    const int r0 = t >> 2;             // 0..63
    const int sg = t & 3;              // 0..3
    const __half* Ag0 = A  + (size_t)(m0 + r0) * K + sg * 8;
    const __half* Ag1 = Ag0 + (size_t)64 * K;
    const __half* Bh0 = Bh + (size_t)(n0 + r0) * K + sg * 8;
    const __half* Bh1 = Bh0 + (size_t)64 * K;
    const __half* Bl0 = SPLITB ? (Bl + (size_t)(n0 + r0) * K + sg * 8) : (const __half*)0;
    const __half* Bl1 = SPLITB ? (Bl0 + (size_t)64 * K) : (const __half*)0;
    const uint32_t d0 = (uint32_t)r0 * (BSTR * 2) + sg * 16;
    const uint32_t d1 = d0 + 64 * (BSTR * 2);

    const uint32_t aoff = ((uint32_t)(wm + (ln & 15)) * BSTR + 8u * (ln >> 4)) * 2;
    const uint32_t boff = TILE_BYTES +
        ((uint32_t)(wn + (ln & 7) + 8 * (ln >> 4)) * BSTR + 8u * ((ln >> 3) & 1)) * 2;

    float acc[2][8][4];
#pragma unroll
    for (int mi = 0; mi < 2; mi++)
#pragma unroll
        for (int nf = 0; nf < 8; nf++)
#pragma unroll
            for (int r = 0; r < 4; r++) acc[mi][nf][r] = 0.0f;

    const int NKT = K / KT;   // 160

    auto issue = [&](int st, int kt) {
        const uint32_t base = sb + (uint32_t)st * stageBytes;
        const size_t ko = (size_t)kt * KT;
        cpa16(base + d0, Ag0 + ko);
        cpa16(base + d1, Ag1 + ko);
        cpa16(base + TILE_BYTES + d0, Bh0 + ko);
        cpa16(base + TILE_BYTES + d1, Bh1 + ko);
        if (useBl) {
            cpa16(base + 2 * TILE_BYTES + d0, Bl0 + ko);
            cpa16(base + 2 * TILE_BYTES + d1, Bl1 + ko);
        }
    };

#pragma unroll
    for (int s = 0; s < STAGES - 1; s++) { issue(s, s); cp_commit(); }

#pragma unroll 1
    for (int kt = 0; kt < NKT; kt++) {
        cp_wait<STAGES - 2>();
        __syncthreads();

        const uint32_t so = sb + (uint32_t)(kt % STAGES) * stageBytes;
#pragma unroll
        for (int ks = 0; ks < 2; ks++) {
            const uint32_t ko = ks * 32;   // 16 halves
            uint32_t af[2][4];
            ldsm4(af[0], so + aoff + ko);
            ldsm4(af[1], so + aoff + 16 * BSTR * 2 + ko);
            uint32_t bh[4][4];
#pragma unroll
            for (int p = 0; p < 4; p++)
                ldsm4(bh[p], so + boff + p * (16 * BSTR * 2) + ko);
            uint32_t bl[4][4];
            if (useBl) {
#pragma unroll
                for (int p = 0; p < 4; p++)
                    ldsm4(bl[p], so + boff + TILE_BYTES + p * (16 * BSTR * 2) + ko);
            }
#pragma unroll
            for (int mi = 0; mi < 2; mi++)
#pragma unroll
                for (int nf = 0; nf < 8; nf++) {
                    mma16(acc[mi][nf], af[mi],
                          bh[nf >> 1][(nf & 1) * 2], bh[nf >> 1][(nf & 1) * 2 + 1]);
                    if (useBl)
                        mma16(acc[mi][nf], af[mi],
                              bl[nf >> 1][(nf & 1) * 2], bl[nf >> 1][(nf & 1) * 2 + 1]);
                }
        }

        const int nk = kt + STAGES - 1;
        if (nk < NKT) issue(nk % STAGES, nk);
        cp_commit();
    }

    // epilogue
    const bool writeLo = SPLITOUT && (n0 < 2 * HID);
#pragma unroll
    for (int mi = 0; mi < 2; mi++) {
        const int r = m0 + wm + mi * 16 + (ln >> 2);
#pragma unroll
        for (int nf = 0; nf < 8; nf++) {
            const int cc = n0 + wn + nf * 8 + (ln & 3) * 2;
            if (SPLITOUT) {
#pragma unroll
                for (int hh = 0; hh < 2; hh++) {
                    const float v0 = acc[mi][nf][2 * hh], v1 = acc[mi][nf][2 * hh + 1];
                    const __half h0 = __float2half_rn(v0), h1 = __float2half_rn(v1);
                    const size_t off = (size_t)(r + 8 * hh) * N + cc;
                    *(uint32_t*)(Chi + off) = packh2(v0, v1);
                    if (writeLo)
                        *(uint32_t*)(Clo + off) =
                            packh2(v0 - __half2float(h0), v1 - __half2float(h1));
                }
            } else {
                *(float2*)(Cf + (size_t)r * N + cc) =
                    make_float2(acc[mi][nf][0], acc[mi][nf][1]);
                *(float2*)(Cf + (size_t)(r + 8) * N + cc) =
                    make_float2(acc[mi][nf][2], acc[mi][nf][3]);
            }
        }
    }
}

// ============================================================================
// Flash attention, fp16 tensor, causal. BQ=128, 256 threads, 1 CTA/SM.
// Double-buffered K/V (Kh,Kl,Vh) prefetched one block ahead via cp.async.
// S = QhKh + QhKl + QlKh; O += P*Vh. Warp-skip of fully-masked blocks.
// Grid (NH, S/BQ), qb reversed for heavy-first dispatch.
// ============================================================================
__global__ __launch_bounds__(256, 1)
void flash16_kernel(const __half* __restrict__ qh, const __half* __restrict__ ql,
                    __half* __restrict__ out) {
    extern __shared__ __align__(16) char sm[];
    const uint32_t sb = smem_u32(sm);
    const uint32_t uQh = sb;
    const uint32_t uQl = sb + Q_TILE;
    const uint32_t uBuf0 = sb + 2 * Q_TILE;

    const int head = blockIdx.x;
    const int qb   = (int)gridDim.y - 1 - (int)blockIdx.y;   // heavy first
    const int q0   = qb * BQ;
    const int t    = threadIdx.x;
    const int w    = t >> 5;
    const int ln   = t & 31;
    const int m0w  = w * 16;
    const float scale = 0.08838834764831845f;   // 1/sqrt(128)

    // cooperative load geometry: row = t>>2 (64 rows per pass), 4 chunks of 16B
    const int lr  = t >> 2;            // 0..63
    const int lc  = (t & 3) * 4;       // chunk base 0,4,8,12

    // ---- Q load (128 rows, hi+lo) ----
#pragma unroll
    for (int pass = 0; pass < 2; pass++) {
        const int r = pass * 64 + lr;
        const size_t go = (size_t)(q0 + r) * QKV_N + head * HD;
        const uint32_t ro = (uint32_t)r * (AQS * 2);
#pragma unroll
        for (int i = 0; i < 4; i++) {
            const int c = lc + i;
            cpa16(uQh + ro + c * 16, qh + go + c * 8);
            cpa16(uQl + ro + c * 16, ql + go + c * 8);
        }
    }
    cp_commit();

    const int nkb = 2 * (qb + 1);

    auto issueKV = [&](int kb) {
        const uint32_t base = uBuf0 + (uint32_t)(kb & 1) * KVBUF;
        const size_t gk = (size_t)(kb * BKV + lr) * QKV_N + HID + head * HD;
        const size_t gv = gk + HID;
        const uint32_t ro = (uint32_t)lr * (AQS * 2);
#pragma unroll
        for (int i = 0; i < 4; i++) {
            const int c = lc + i;
            cpa16(base + ro + c * 16, qh + gk + c * 8);                    // Kh
            cpa16(base + KV_TILE + ro + c * 16, ql + gk + c * 8);          // Kl
            cpa16(base + 2 * KV_TILE + ro + c * 16, qh + gv + c * 8);      // Vh
        }
    };

    issueKV(0);
    cp_commit();

    float m_i[2] = {-1e30f, -1e30f};
    float l_i[2] = {0.0f, 0.0f};
    float o[16][4];
#pragma unroll
    for (int d = 0; d < 16; d++)
#pragma unroll
        for (int r = 0; r < 4; r++) o[d][r] = 0.0f;

    const uint32_t aQ = ((uint32_t)(m0w + (ln & 15)) * AQS + 8u * (ln >> 4)) * 2;
    const uint32_t bK = ((uint32_t)((ln & 7) + 8 * (ln >> 4)) * AQS + 8u * ((ln >> 3) & 1)) * 2;
    const uint32_t bV = ((uint32_t)((ln & 7) + 8 * ((ln >> 3) & 1)) * AQS + 8u * (ln >> 4)) * 2;

    const int r1g = q0 + m0w + (ln >> 2);
    const int r2g = r1g + 8;

#pragma unroll 1
    for (int kb = 0; kb < nkb; kb++) {
        const int k0 = kb * BKV;

        if (kb + 1 < nkb) {
            issueKV(kb + 1);
            cp_commit();
            cp_wait<1>();
        } else {
            cp_wait<0>();
        }
        __syncthreads();   // K/V(kb) visible to all

        // warp-level skip: all columns of this block beyond this warp's rows
        if (k0 <= q0 + m0w + 15) {
            const uint32_t cKh = uBuf0 + (uint32_t)(kb & 1) * KVBUF;
            const uint32_t cKl = cKh + KV_TILE;
            const uint32_t cVh = cKh + 2 * KV_TILE;

            // ---- S = Q K^T (compensated) ----
            float s[8][4];
#pragma unroll
            for (int nf = 0; nf < 8; nf++)
#pragma unroll
                for (int r = 0; r < 4; r++) s[nf][r] = 0.0f;

#pragma unroll
            for (int ks = 0; ks < 8; ks++) {
                const uint32_t ko = ks * 32;
                uint32_t qhf[4], qlf[4];
                ldsm4(qhf, uQh + aQ + ko);
                ldsm4(qlf, uQl + aQ + ko);
                uint32_t kh[4][4], kl[4][4];
#pragma unroll
                for (int p = 0; p < 4; p++) {
                    ldsm4(kh[p], cKh + bK + p * (16 * AQS * 2) + ko);
                    ldsm4(kl[p], cKl + bK + p * (16 * AQS * 2) + ko);
                }
#pragma unroll
                for (int nf = 0; nf < 8; nf++) {
                    const uint32_t h0 = kh[nf >> 1][(nf & 1) * 2];
                    const uint32_t h1 = kh[nf >> 1][(nf & 1) * 2 + 1];
                    const uint32_t l0 = kl[nf >> 1][(nf & 1) * 2];
                    const uint32_t l1 = kl[nf >> 1][(nf & 1) * 2 + 1];
                    mma16(s[nf], qhf, h0, h1);
                    mma16(s[nf], qhf, l0, l1);
                    mma16(s[nf], qlf, h0, h1);
                }
            }

            // ---- scale + causal mask + online softmax ----
            const bool needMask = (k0 + BKV - 1 > q0 + m0w);
            float mx1 = -1e30f, mx2 = -1e30f;
#pragma unroll
            for (int nf = 0; nf < 8; nf++) {
                float v0 = s[nf][0] * scale, v1 = s[nf][1] * scale;
                float v2 = s[nf][2] * scale, v3 = s[nf][3] * scale;
                if (needMask) {
                    const int cb = k0 + nf * 8 + 2 * (ln & 3);
                    if (cb     > r1g) v0 = -1e30f;
                    if (cb + 1 > r1g) v1 = -1e30f;
                    if (cb     > r2g) v2 = -1e30f;
                    if (cb + 1 > r2g) v3 = -1e30f;
                }
                s[nf][0] = v0; s[nf][1] = v1; s[nf][2] = v2; s[nf][3] = v3;
                mx1 = fmaxf(mx1, fmaxf(v0, v1));
                mx2 = fmaxf(mx2, fmaxf(v2, v3));
            }
            mx1 = fmaxf(mx1, __shfl_xor_sync(0xffffffffu, mx1, 1));
            mx1 = fmaxf(mx1, __shfl_xor_sync(0xffffffffu, mx1, 2));
            mx2 = fmaxf(mx2, __shfl_xor_sync(0xffffffffu, mx2, 1));
            mx2 = fmaxf(mx2, __shfl_xor_sync(0xffffffffu, mx2, 2));

            const float mn1 = fmaxf(m_i[0], mx1);
            const float mn2 = fmaxf(m_i[1], mx2);
            const float corr1 = __expf(m_i[0] - mn1);
            const float corr2 = __expf(m_i[1] - mn2);
            m_i[0] = mn1; m_i[1] = mn2;

            float rs1 = 0.0f, rs2 = 0.0f;
#pragma unroll
            for (int nf = 0; nf < 8; nf++) {
                float p0 = __expf(s[nf][0] - mn1);
                float p1 = __expf(s[nf][1] - mn1);
                float p2 = __expf(s[nf][2] - mn2);
                float p3 = __expf(s[nf][3] - mn2);
                rs1 += p0 + p1; rs2 += p2 + p3;
                s[nf][0] = p0; s[nf][1] = p1; s[nf][2] = p2; s[nf][3] = p3;
            }
            rs1 += __shfl_xor_sync(0xffffffffu, rs1, 1);
            rs1 += __shfl_xor_sync(0xffffffffu, rs1, 2);
            rs2 += __shfl_xor_sync(0xffffffffu, rs2, 1);
            rs2 += __shfl_xor_sync(0xffffffffu, rs2, 2);
            l_i[0] = l_i[0] * corr1 + rs1;
            l_i[1] = l_i[1] * corr2 + rs2;

#pragma unroll
            for (int d = 0; d < 16; d++) {
                o[d][0] *= corr1; o[d][1] *= corr1;
                o[d][2] *= corr2; o[d][3] *= corr2;
            }

            // ---- P repack (C-frags -> A-frags, registers) ----
            uint32_t pa[4][4];
#pragma unroll
            for (int tk = 0; tk < 4; tk++) {
                pa[tk][0] = packh2(s[2 * tk][0],     s[2 * tk][1]);
                pa[tk][1] = packh2(s[2 * tk][2],     s[2 * tk][3]);
                pa[tk][2] = packh2(s[2 * tk + 1][0], s[2 * tk + 1][1]);
                pa[tk][3] = packh2(s[2 * tk + 1][2], s[2 * tk + 1][3]);
            }

            // ---- O += P * Vh ----
#pragma unroll
            for (int tk = 0; tk < 4; tk++) {
                const uint32_t rowo = (uint32_t)(16 * tk) * AQS * 2;
#pragma unroll
                for (int p = 0; p < 8; p++) {
                    uint32_t vh[4];
                    ldsm4t(vh, cVh + rowo + bV + (uint32_t)p * 32);
                    mma16(o[2 * p],     pa[tk], vh[0], vh[1]);
                    mma16(o[2 * p + 1], pa[tk], vh[2], vh[3]);
                }
            }
        }

        __syncthreads();   // all warps done with buf[kb&1] before it is reissued
    }

    // ---- epilogue: fp16 output ----
    const float inv1 = 1.0f / l_i[0];
    const float inv2 = 1.0f / l_i[1];
#pragma unroll
    for (int d = 0; d < 16; d++) {
        const int cc = head * HD + d * 8 + 2 * (ln & 3);
        *(__half2*)(out + (size_t)r1g * HID + cc) =
            __floats2half2_rn(o[d][0] * inv1, o[d][1] * inv1);
        *(__half2*)(out + (size_t)r2g * HID + cc) =
            __floats2half2_rn(o[d][2] * inv2, o[d][3] * inv2);
    }
}

// ============================================================================
// Launch
// ============================================================================
extern "C" void kernel_launch(void* const* d_in, const int* in_sizes, int n_in,
                              void* d_out, int out_size) {
    const float* hidden = (const float*)d_in[0];
    const float* wpack  = (const float*)d_in[1];
    const float* wo     = (const float*)d_in[2];
    float* out = (float*)d_out;

    __half *qkvh, *qkvl, *h16, *wph, *wpl, *wo16, *at16;
    cudaGetSymbolAddress((void**)&qkvh, g_qkvh);
    cudaGetSymbolAddress((void**)&qkvl, g_qkvl);
    cudaGetSymbolAddress((void**)&h16,  g_h16);
    cudaGetSymbolAddress((void**)&wph,  g_wp_hi);
    cudaGetSymbolAddress((void**)&wpl,  g_wp_lo);
    cudaGetSymbolAddress((void**)&wo16, g_wo16);
    cudaGetSymbolAddress((void**)&at16, g_attno16);

    cudaFuncSetAttribute((const void*)gemm16p<true, true>,
                         cudaFuncAttributeMaxDynamicSharedMemorySize, GEMM_SMEM_SPLIT);
    cudaFuncSetAttribute((const void*)gemm16p<false, false>,
                         cudaFuncAttributeMaxDynamicSharedMemorySize, GEMM_SMEM_SINGLE);
    cudaFuncSetAttribute((const void*)flash16_kernel,
                         cudaFuncAttributeMaxDynamicSharedMemorySize, FSMEM);

    // 0. pre-conversions: H -> fp16; Wpack Q,K rows -> hi/lo; V rows + Wo -> fp16
    const size_t qkRows = (size_t)2 * HID * HID;   // first 10240 rows of Wpack
    cvt_one_kernel<<<4096, 256>>>((const float4*)hidden, (uint2*)h16,
                                  (int)((size_t)S_LEN * HID / 4));
    cvt_split_kernel<<<8192, 256>>>((const float4*)wpack, (uint2*)wph, (uint2*)wpl,
                                    (int)(qkRows / 4));
    cvt_one_kernel<<<4096, 256>>>((const float4*)(wpack + qkRows),
                                  (uint2*)(wph + qkRows),
                                  (int)((size_t)HID * HID / 4));
    cvt_one_kernel<<<4096, 256>>>((const float4*)wo, (uint2*)wo16,
                                  (int)((size_t)HID * HID / 4));

    // 1. QKV projection (split-B for Q,K tiles; split-out hi/lo)
    dim3 g1(S_LEN / MT, QKV_N / NT);
    gemm16p<true, true><<<g1, 256, GEMM_SMEM_SPLIT>>>(
        h16, wph, wpl, nullptr, qkvh, qkvl, S_LEN, QKV_N, HID);

    // 2. Causal flash attention (BQ=128, prefetched K/V) -> fp16
    dim3 g2(NH, S_LEN / BQ);
    flash16_kernel<<<g2, 256, FSMEM>>>(qkvh, qkvl, at16);

    // 3. Output projection (single fp16) -> fp32 out
    dim3 g3(S_LEN / MT, HID / NT);
    gemm16p<false, false><<<g3, 256, GEMM_SMEM_SINGLE>>>(
        at16, wo16, nullptr, out, nullptr, nullptr, S_LEN, HID, HID);
}